// round 1
// baseline (speedup 1.0000x reference)
#include <cuda_runtime.h>
#include <cstdint>

// Problem-fixed sizes (from reference setup_inputs)
#define N_NODES 50000
#define F_INF   512
#define H_DIM   128
#define E_MAX   1600000

// Scratch (device globals: allocation-free per harness rules)
__device__ float g_deg [N_NODES];
__device__ float g_dinv[N_NODES];
__device__ float g_h   [(size_t)N_NODES * H_DIM];  // 25.6 MB
__device__ float g_agg [(size_t)N_NODES * H_DIM];  // 25.6 MB

// ---------------------------------------------------------------------------
// Degree / normalization
// ---------------------------------------------------------------------------
__global__ void k_init_deg(int n) {
    int i = blockIdx.x * blockDim.x + threadIdx.x;
    if (i < n) g_deg[i] = 1.0f;   // self-loop weight
}

__global__ void k_deg_accum(const int* __restrict__ dst,
                            const float* __restrict__ w, int E) {
    int e = blockIdx.x * blockDim.x + threadIdx.x;
    if (e < E) atomicAdd(&g_deg[dst[e]], w[e]);
}

__global__ void k_dinv(int n) {
    int i = blockIdx.x * blockDim.x + threadIdx.x;
    if (i < n) {
        float d = g_deg[i];
        g_dinv[i] = (d > 0.0f) ? rsqrtf(d) : 0.0f;
    }
}

// ---------------------------------------------------------------------------
// SGEMM: C[M,Nn] = A[M,K] * B[K,Nn]  (all row-major), 128x128 tile, 8x8 micro
// MODE 0: A = x, writes g_h and g_agg = h*dinv^2 + b_conv  (self-loop init)
// MODE 1: A = g_agg, writes C = out + b_lin
// ---------------------------------------------------------------------------
template <int MODE>
__global__ __launch_bounds__(256)
void sgemm128(const float* __restrict__ A_in,
              const float* __restrict__ B,
              const float* __restrict__ bias,
              float* __restrict__ C,
              int M, int Nn, int K) {
    constexpr int BM = 128, BN = 128, BK = 16, TM = 8, TN = 8;
    __shared__ float As[BK][BM];
    __shared__ float Bs[BK][BN];

    const float* A = (MODE == 0) ? A_in : g_agg;

    int tid = threadIdx.x;
    int tx = tid & 15;          // 0..15
    int ty = tid >> 4;          // 0..15
    int rowBase = blockIdx.y * BM;
    int colBase = blockIdx.x * BN;

    float acc[TM][TN];
#pragma unroll
    for (int m = 0; m < TM; m++)
#pragma unroll
        for (int n = 0; n < TN; n++) acc[m][n] = 0.0f;

    for (int k0 = 0; k0 < K; k0 += BK) {
#pragma unroll
        for (int l = 0; l < 2; l++) {
            int idx = tid + l * 256;          // 0..511 (float4 index)
            // A tile: 128 rows x 16 cols = 512 float4
            int ra = idx >> 2;                // 0..127
            int ca = (idx & 3) << 2;          // 0,4,8,12
            int grow = rowBase + ra;
            float4 v;
            if (grow < M)
                v = *(const float4*)(A + (size_t)grow * K + k0 + ca);
            else
                v = make_float4(0.f, 0.f, 0.f, 0.f);
            As[ca + 0][ra] = v.x;
            As[ca + 1][ra] = v.y;
            As[ca + 2][ra] = v.z;
            As[ca + 3][ra] = v.w;
            // B tile: 16 rows x 128 cols = 512 float4
            int rb = idx >> 5;                // 0..15
            int cb = (idx & 31) << 2;         // 0..124
            float4 u = *(const float4*)(B + (size_t)(k0 + rb) * Nn + colBase + cb);
            *(float4*)&Bs[rb][cb] = u;
        }
        __syncthreads();

#pragma unroll
        for (int kk = 0; kk < BK; kk++) {
            float ar[TM], br[TN];
#pragma unroll
            for (int m = 0; m < TM; m++) ar[m] = As[kk][ty * TM + m];
#pragma unroll
            for (int n = 0; n < TN; n++) br[n] = Bs[kk][tx * TN + n];
#pragma unroll
            for (int m = 0; m < TM; m++)
#pragma unroll
                for (int n = 0; n < TN; n++)
                    acc[m][n] = fmaf(ar[m], br[n], acc[m][n]);
        }
        __syncthreads();
    }

    // Epilogue
#pragma unroll
    for (int m = 0; m < TM; m++) {
        int grow = rowBase + ty * TM + m;
        if (grow >= M) continue;
        float sc = 0.0f;
        if (MODE == 0) {
            float di = g_dinv[grow];
            sc = di * di;
        }
#pragma unroll
        for (int n = 0; n < TN; n += 4) {
            int gcol = colBase + tx * TN + n;
            float4 v = make_float4(acc[m][n], acc[m][n + 1], acc[m][n + 2], acc[m][n + 3]);
            float4 bb = *(const float4*)(bias + gcol);
            if (MODE == 0) {
                // store h
                *(float4*)(g_h + (size_t)grow * Nn + gcol) = v;
                // init agg with self-loop contribution + conv bias
                float4 a2 = make_float4(v.x * sc + bb.x, v.y * sc + bb.y,
                                        v.z * sc + bb.z, v.w * sc + bb.w);
                *(float4*)(g_agg + (size_t)grow * Nn + gcol) = a2;
            } else {
                v.x += bb.x; v.y += bb.y; v.z += bb.z; v.w += bb.w;
                *(float4*)(C + (size_t)grow * Nn + gcol) = v;
            }
        }
    }
}

// ---------------------------------------------------------------------------
// Edge scatter: one warp per edge. Gather h[src] (128 floats = 1 float4/lane),
// scale by norm, vector-reduce into agg[dst].
// ---------------------------------------------------------------------------
__global__ __launch_bounds__(256)
void k_scatter(const int* __restrict__ src, const int* __restrict__ dst,
               const float* __restrict__ w, int E) {
    int gwarp = (blockIdx.x * blockDim.x + threadIdx.x) >> 5;
    int lane = threadIdx.x & 31;
    if (gwarp >= E) return;

    int s = __ldg(&src[gwarp]);
    int d = __ldg(&dst[gwarp]);
    float coef = g_dinv[s] * __ldg(&w[gwarp]) * g_dinv[d];
    if (coef == 0.0f) return;

    float4 v = *(const float4*)(g_h + (size_t)s * H_DIM + lane * 4);
    v.x *= coef; v.y *= coef; v.z *= coef; v.w *= coef;

    float* ap = g_agg + (size_t)d * H_DIM + lane * 4;
    asm volatile("red.global.add.v4.f32 [%0], {%1,%2,%3,%4};"
                 :: "l"(ap), "f"(v.x), "f"(v.y), "f"(v.z), "f"(v.w)
                 : "memory");
}

// ---------------------------------------------------------------------------
extern "C" void kernel_launch(void* const* d_in, const int* in_sizes, int n_in,
                              void* d_out, int out_size) {
    const float* x  = (const float*)d_in[0];   // [N, 512]
    const int*   ei = (const int*)  d_in[1];   // [2, E]
    const float* ew = (const float*)d_in[2];   // [E]
    const float* Wc = (const float*)d_in[3];   // [512, 128]
    const float* bc = (const float*)d_in[4];   // [128]
    const float* Wl = (const float*)d_in[5];   // [128, 512]
    const float* bl = (const float*)d_in[6];   // [512]
    float* out = (float*)d_out;                // [N, 512]

    int E = in_sizes[2];
    int n = in_sizes[0] / F_INF;
    const int* src = ei;
    const int* dst = ei + E;

    // 1) degrees + normalization
    k_init_deg<<<(n + 255) / 256, 256>>>(n);
    k_deg_accum<<<(E + 255) / 256, 256>>>(dst, ew, E);
    k_dinv<<<(n + 255) / 256, 256>>>(n);

    // 2) h = x @ W_conv ; agg = h*dinv^2 + b_conv
    {
        dim3 grid(H_DIM / 128, (n + 127) / 128);
        sgemm128<0><<<grid, 256>>>(x, Wc, bc, nullptr, n, H_DIM, F_INF);
    }

    // 3) edge scatter into agg
    {
        int warpsPerBlock = 256 / 32;
        int blocks = (E + warpsPerBlock - 1) / warpsPerBlock;
        k_scatter<<<blocks, 256>>>(src, dst, ew, E);
    }

    // 4) out = agg @ W_lin + b_lin
    {
        dim3 grid(F_INF / 128, (n + 127) / 128);
        sgemm128<1><<<grid, 256>>>(nullptr, Wl, bl, out, n, F_INF, H_DIM);
    }
}

// round 3
// speedup vs baseline: 1.2921x; 1.2921x over previous
#include <cuda_runtime.h>
#include <cuda_bf16.h>
#include <cstdint>

#define N_NODES 50000
#define F_INF   512
#define H_DIM   128

// ---------------------------------------------------------------------------
// Device scratch (allocation-free rule: device globals)
// ---------------------------------------------------------------------------
__device__ float g_deg [N_NODES];
__device__ float g_dinv[N_NODES];
__device__ __align__(16) float g_h   [(size_t)N_NODES * H_DIM];   // 25.6 MB
__device__ __align__(16) float g_agg [(size_t)N_NODES * H_DIM];   // 25.6 MB
__device__ __align__(16) __nv_bfloat16 g_wch [H_DIM * F_INF];  // Wc^T [128,512] hi
__device__ __align__(16) __nv_bfloat16 g_wcl [H_DIM * F_INF];  // lo
__device__ __align__(16) __nv_bfloat16 g_wlh [F_INF * H_DIM];  // Wl^T [512,128] hi
__device__ __align__(16) __nv_bfloat16 g_wll [F_INF * H_DIM];  // lo

#define SMEM_SWIZZLE_128B(off) ((off) ^ (((off) >> 3) & 0x70))

__device__ __forceinline__ uint32_t smem_to_u32(const void* p) {
    uint32_t a;
    asm("{ .reg .u64 t; cvta.to.shared.u64 t, %1; cvt.u32.u64 %0, t; }"
        : "=r"(a) : "l"(p));
    return a;
}

__device__ __forceinline__ void ldsm_x4(uint32_t* r, uint32_t addr) {
    asm volatile("ldmatrix.sync.aligned.m8n8.x4.shared.b16 {%0,%1,%2,%3}, [%4];"
                 : "=r"(r[0]), "=r"(r[1]), "=r"(r[2]), "=r"(r[3]) : "r"(addr));
}

__device__ __forceinline__ void mma_bf16(float* c, const uint32_t* a,
                                         uint32_t b0, uint32_t b1) {
    asm volatile(
        "mma.sync.aligned.m16n8k16.row.col.f32.bf16.bf16.f32 "
        "{%0,%1,%2,%3}, {%4,%5,%6,%7}, {%8,%9}, {%0,%1,%2,%3};"
        : "+f"(c[0]), "+f"(c[1]), "+f"(c[2]), "+f"(c[3])
        : "r"(a[0]), "r"(a[1]), "r"(a[2]), "r"(a[3]), "r"(b0), "r"(b1));
}

__device__ __forceinline__ uint32_t pack_bf16(float x, float y) {
    __nv_bfloat16 bx = __float2bfloat16(x), by = __float2bfloat16(y);
    return (uint32_t)__bfloat16_as_ushort(bx) |
           ((uint32_t)__bfloat16_as_ushort(by) << 16);
}

// ---------------------------------------------------------------------------
// Degree / normalization
// ---------------------------------------------------------------------------
__global__ void k_init_deg(int n) {
    int i = blockIdx.x * blockDim.x + threadIdx.x;
    if (i < n) g_deg[i] = 1.0f;
}
__global__ void k_deg_accum(const int* __restrict__ dst, const float* __restrict__ w, int E) {
    int e = blockIdx.x * blockDim.x + threadIdx.x;
    if (e < E) atomicAdd(&g_deg[dst[e]], w[e]);
}
__global__ void k_dinv(int n) {
    int i = blockIdx.x * blockDim.x + threadIdx.x;
    if (i < n) {
        float d = g_deg[i];
        g_dinv[i] = (d > 0.0f) ? rsqrtf(d) : 0.0f;
    }
}

// Transposed weight split: W [K,N] row-major -> out [N,K] bf16 hi/lo
__global__ void k_split_wT(const float* __restrict__ W,
                           __nv_bfloat16* __restrict__ hiT,
                           __nv_bfloat16* __restrict__ loT, int K, int N) {
    int idx = blockIdx.x * blockDim.x + threadIdx.x;
    if (idx >= K * N) return;
    int n = idx / K, k = idx % K;
    float v = W[(size_t)k * N + n];
    __nv_bfloat16 h = __float2bfloat16(v);
    hiT[(size_t)n * K + k] = h;
    loT[(size_t)n * K + k] = __float2bfloat16(v - __bfloat162float(h));
}

// ---------------------------------------------------------------------------
// mma.sync bf16 split GEMM: C[M,N] = A[M,K] (fp32, converted on load) * B[N,K]^T
// CTA tile 128x128; 8 warps (4 M x 2 N), warp tile 32x64; K chunk 64.
// MODE 0: A = x [M,512], B = WcT; epilogue -> g_h, g_agg = h*dinv^2 + b_conv
// MODE 1: A = g_agg [M,128], B = WlT; epilogue -> out + b_lin
// ---------------------------------------------------------------------------
template <int MODE>
__global__ __launch_bounds__(256)
void mma_gemm(const float* __restrict__ A,
              const __nv_bfloat16* __restrict__ b_hi,
              const __nv_bfloat16* __restrict__ b_lo,
              const float* __restrict__ bias,
              float* __restrict__ outp,
              int M, int K) {
    extern __shared__ char smem[];
    constexpr int SM_AH = 0, SM_AL = 16384, SM_BH = 32768, SM_BL = 49152;

    uint32_t sbase = smem_to_u32(smem);
    int tid = threadIdx.x;
    int wid = tid >> 5, lane = tid & 31;
    int wm = wid & 3, wn = wid >> 2;
    int rowBase = blockIdx.y * 128;
    int colBase = blockIdx.x * 128;

    float acc[2][8][4];
#pragma unroll
    for (int i = 0; i < 2; i++)
#pragma unroll
        for (int j = 0; j < 8; j++)
#pragma unroll
            for (int k = 0; k < 4; k++) acc[i][j][k] = 0.0f;

    uint32_t lr = lane & 7, lg = lane >> 3;

    int nchunk = K >> 6;
    for (int c = 0; c < nchunk; c++) {
        int k0 = c << 6;
        // ---- A tile: 128 rows x 64 k, fp32 -> bf16 hi/lo, swizzled ----
        for (int t = tid; t < 1024; t += 256) {
            int r = t >> 3, q = t & 7;
            int grow = rowBase + r;
            float4 v0 = make_float4(0.f, 0.f, 0.f, 0.f), v1 = v0;
            if (grow < M) {
                const float* ap = A + (size_t)grow * K + k0 + q * 8;
                v0 = *(const float4*)ap;
                v1 = *(const float4*)(ap + 4);
            }
            uint4 hi, lo;
            hi.x = pack_bf16(v0.x, v0.y); hi.y = pack_bf16(v0.z, v0.w);
            hi.z = pack_bf16(v1.x, v1.y); hi.w = pack_bf16(v1.z, v1.w);
            float r0 = v0.x - __bfloat162float(__ushort_as_bfloat16((unsigned short)(hi.x & 0xFFFF)));
            float r1 = v0.y - __bfloat162float(__ushort_as_bfloat16((unsigned short)(hi.x >> 16)));
            float r2 = v0.z - __bfloat162float(__ushort_as_bfloat16((unsigned short)(hi.y & 0xFFFF)));
            float r3 = v0.w - __bfloat162float(__ushort_as_bfloat16((unsigned short)(hi.y >> 16)));
            float r4 = v1.x - __bfloat162float(__ushort_as_bfloat16((unsigned short)(hi.z & 0xFFFF)));
            float r5 = v1.y - __bfloat162float(__ushort_as_bfloat16((unsigned short)(hi.z >> 16)));
            float r6 = v1.z - __bfloat162float(__ushort_as_bfloat16((unsigned short)(hi.w & 0xFFFF)));
            float r7 = v1.w - __bfloat162float(__ushort_as_bfloat16((unsigned short)(hi.w >> 16)));
            lo.x = pack_bf16(r0, r1); lo.y = pack_bf16(r2, r3);
            lo.z = pack_bf16(r4, r5); lo.w = pack_bf16(r6, r7);
            uint32_t sw = SMEM_SWIZZLE_128B((uint32_t)(r * 128 + q * 16));
            *(uint4*)(smem + SM_AH + sw) = hi;
            *(uint4*)(smem + SM_AL + sw) = lo;
        }
        // ---- B tiles: bf16 hi/lo from WT [N,K], swizzled ----
        for (int t = tid; t < 2048; t += 256) {
            int which = t >> 10;          // 0: hi, 1: lo
            int r = (t >> 3) & 127, q = t & 7;
            const __nv_bfloat16* sp = which ? b_lo : b_hi;
            uint4 v = *(const uint4*)(sp + (size_t)(colBase + r) * K + k0 + q * 8);
            uint32_t sw = SMEM_SWIZZLE_128B((uint32_t)(r * 128 + q * 16));
            *(uint4*)(smem + (which ? SM_BL : SM_BH) + sw) = v;
        }
        __syncthreads();

#pragma unroll
        for (int s = 0; s < 4; s++) {
            uint32_t ah[2][4], al[2][4], bh[4][4], bl[4][4];
#pragma unroll
            for (int fm = 0; fm < 2; fm++) {
                uint32_t row = (uint32_t)(wm * 32 + fm * 16 + ((lg & 1) << 3) + lr);
                uint32_t kb = (uint32_t)(s * 32 + ((lg >> 1) << 4));
                uint32_t off = SMEM_SWIZZLE_128B(row * 128 + kb);
                ldsm_x4(ah[fm], sbase + SM_AH + off);
                ldsm_x4(al[fm], sbase + SM_AL + off);
            }
#pragma unroll
            for (int fn2 = 0; fn2 < 4; fn2++) {
                uint32_t row = (uint32_t)(wn * 64 + fn2 * 16 + ((lg >> 1) << 3) + lr);
                uint32_t kb = (uint32_t)(s * 32 + ((lg & 1) << 4));
                uint32_t off = SMEM_SWIZZLE_128B(row * 128 + kb);
                ldsm_x4(bh[fn2], sbase + SM_BH + off);
                ldsm_x4(bl[fn2], sbase + SM_BL + off);
            }
#pragma unroll
            for (int fm = 0; fm < 2; fm++)
#pragma unroll
                for (int fn2 = 0; fn2 < 4; fn2++)
#pragma unroll
                    for (int nh = 0; nh < 2; nh++) {
                        float* cc = acc[fm][fn2 * 2 + nh];
                        mma_bf16(cc, ah[fm], bh[fn2][nh * 2], bh[fn2][nh * 2 + 1]);
                        mma_bf16(cc, ah[fm], bl[fn2][nh * 2], bl[fn2][nh * 2 + 1]);
                        mma_bf16(cc, al[fm], bh[fn2][nh * 2], bh[fn2][nh * 2 + 1]);
                    }
        }
        __syncthreads();
    }

    // ---- Epilogue ----
    int gq = lane >> 2;          // 0..7 (row within 8)
    int tq = lane & 3;           // 0..3 (col pair)
#pragma unroll
    for (int fm = 0; fm < 2; fm++) {
#pragma unroll
        for (int half = 0; half < 2; half++) {
            int row = rowBase + wm * 32 + fm * 16 + half * 8 + gq;
            if (row >= M) continue;
            float sc = 0.0f;
            if (MODE == 0) { float di = g_dinv[row]; sc = di * di; }
#pragma unroll
            for (int fn = 0; fn < 8; fn++) {
                int col = colBase + wn * 64 + fn * 8 + tq * 2;
                float c0 = acc[fm][fn][half * 2 + 0];
                float c1 = acc[fm][fn][half * 2 + 1];
                if (MODE == 0) {
                    // GEMM1: N = 128, colBase = 0
                    float2 hv = make_float2(c0, c1);
                    *(float2*)(g_h + (size_t)row * 128 + col) = hv;
                    float b0 = __ldg(bias + col), b1 = __ldg(bias + col + 1);
                    float2 av = make_float2(fmaf(c0, sc, b0), fmaf(c1, sc, b1));
                    *(float2*)(g_agg + (size_t)row * 128 + col) = av;
                } else {
                    float b0 = __ldg(bias + col), b1 = __ldg(bias + col + 1);
                    *(float2*)(outp + (size_t)row * 512 + col) = make_float2(c0 + b0, c1 + b1);
                }
            }
        }
    }
}

// ---------------------------------------------------------------------------
// Edge scatter: one warp per edge, vector red into g_agg
// ---------------------------------------------------------------------------
__global__ __launch_bounds__(256)
void k_scatter(const int* __restrict__ src, const int* __restrict__ dst,
               const float* __restrict__ w, int E) {
    int gwarp = (blockIdx.x * blockDim.x + threadIdx.x) >> 5;
    int lane = threadIdx.x & 31;
    if (gwarp >= E) return;
    int s = __ldg(&src[gwarp]);
    int d = __ldg(&dst[gwarp]);
    float coef = g_dinv[s] * __ldg(&w[gwarp]) * g_dinv[d];
    if (coef == 0.0f) return;
    float4 v = *(const float4*)(g_h + (size_t)s * H_DIM + lane * 4);
    v.x *= coef; v.y *= coef; v.z *= coef; v.w *= coef;
    float* ap = g_agg + (size_t)d * H_DIM + lane * 4;
    asm volatile("red.global.add.v4.f32 [%0], {%1,%2,%3,%4};"
                 :: "l"(ap), "f"(v.x), "f"(v.y), "f"(v.z), "f"(v.w)
                 : "memory");
}

// ---------------------------------------------------------------------------
extern "C" void kernel_launch(void* const* d_in, const int* in_sizes, int n_in,
                              void* d_out, int out_size) {
    const float* x  = (const float*)d_in[0];
    const int*   ei = (const int*)  d_in[1];
    const float* ew = (const float*)d_in[2];
    const float* Wc = (const float*)d_in[3];  // [512,128]
    const float* bc = (const float*)d_in[4];
    const float* Wl = (const float*)d_in[5];  // [128,512]
    const float* bl = (const float*)d_in[6];
    float* out = (float*)d_out;

    int E = in_sizes[2];
    int n = in_sizes[0] / F_INF;
    const int* src = ei;
    const int* dst = ei + E;

    const int SMEM_BYTES = 65536;
    cudaFuncSetAttribute(mma_gemm<0>, cudaFuncAttributeMaxDynamicSharedMemorySize, SMEM_BYTES);
    cudaFuncSetAttribute(mma_gemm<1>, cudaFuncAttributeMaxDynamicSharedMemorySize, SMEM_BYTES);

    __nv_bfloat16 *wch, *wcl, *wlh, *wll;
    float *dagg;
    cudaGetSymbolAddress((void**)&wch, g_wch);
    cudaGetSymbolAddress((void**)&wcl, g_wcl);
    cudaGetSymbolAddress((void**)&wlh, g_wlh);
    cudaGetSymbolAddress((void**)&wll, g_wll);
    cudaGetSymbolAddress((void**)&dagg, g_agg);

    // 1) degree + norm
    k_init_deg<<<(n + 255) / 256, 256>>>(n);
    k_deg_accum<<<(E + 255) / 256, 256>>>(dst, ew, E);
    k_dinv<<<(n + 255) / 256, 256>>>(n);

    // 2) weight splits (transposed, bf16 hi/lo)
    k_split_wT<<<(F_INF * H_DIM + 255) / 256, 256>>>(Wc, wch, wcl, F_INF, H_DIM);
    k_split_wT<<<(F_INF * H_DIM + 255) / 256, 256>>>(Wl, wlh, wll, H_DIM, F_INF);

    // 3) GEMM1: h = x @ Wc ; agg = h*dinv^2 + b_conv  (x converted in-kernel)
    {
        dim3 grid(1, (n + 127) / 128);
        mma_gemm<0><<<grid, 256, SMEM_BYTES>>>(x, wch, wcl, bc, nullptr, n, F_INF);
    }

    // 4) edge scatter into agg
    {
        int blocks = (E + 7) / 8;
        k_scatter<<<blocks, 256>>>(src, dst, ew, E);
    }

    // 5) GEMM2: out = agg @ Wl + b_lin  (agg converted in-kernel)
    {
        dim3 grid(F_INF / 128, (n + 127) / 128);
        mma_gemm<1><<<grid, 256, SMEM_BYTES>>>(dagg, wlh, wll, bl, out, n, H_DIM);
    }
}

// round 4
// speedup vs baseline: 1.4390x; 1.1137x over previous
#include <cuda_runtime.h>
#include <cuda_bf16.h>
#include <cstdint>

#define N_NODES 50000
#define F_INF   512
#define H_DIM   128
#define E_MAX   1600000

// ---------------------------------------------------------------------------
// Device scratch (allocation-free rule: device globals)
// ---------------------------------------------------------------------------
__device__ float g_deg [N_NODES];
__device__ float g_dinv[N_NODES];
__device__ int   g_cnt [N_NODES];
__device__ int   g_off [N_NODES + 1];
__device__ int   g_cur [N_NODES];
__device__ __align__(16) uint2 g_edges[E_MAX];                   // (src, coef) 12.8 MB
__device__ __align__(16) float g_h   [(size_t)N_NODES * H_DIM];  // 25.6 MB
__device__ __align__(16) float g_agg [(size_t)N_NODES * H_DIM];  // 25.6 MB
__device__ __align__(16) __nv_bfloat16 g_wch [H_DIM * F_INF];
__device__ __align__(16) __nv_bfloat16 g_wcl [H_DIM * F_INF];
__device__ __align__(16) __nv_bfloat16 g_wlh [F_INF * H_DIM];
__device__ __align__(16) __nv_bfloat16 g_wll [F_INF * H_DIM];

#define SMEM_SWIZZLE_128B(off) ((off) ^ (((off) >> 3) & 0x70))

__device__ __forceinline__ uint32_t smem_to_u32(const void* p) {
    uint32_t a;
    asm("{ .reg .u64 t; cvta.to.shared.u64 t, %1; cvt.u32.u64 %0, t; }"
        : "=r"(a) : "l"(p));
    return a;
}

__device__ __forceinline__ void ldsm_x4(uint32_t* r, uint32_t addr) {
    asm volatile("ldmatrix.sync.aligned.m8n8.x4.shared.b16 {%0,%1,%2,%3}, [%4];"
                 : "=r"(r[0]), "=r"(r[1]), "=r"(r[2]), "=r"(r[3]) : "r"(addr));
}

__device__ __forceinline__ void mma_bf16(float* c, const uint32_t* a,
                                         uint32_t b0, uint32_t b1) {
    asm volatile(
        "mma.sync.aligned.m16n8k16.row.col.f32.bf16.bf16.f32 "
        "{%0,%1,%2,%3}, {%4,%5,%6,%7}, {%8,%9}, {%0,%1,%2,%3};"
        : "+f"(c[0]), "+f"(c[1]), "+f"(c[2]), "+f"(c[3])
        : "r"(a[0]), "r"(a[1]), "r"(a[2]), "r"(a[3]), "r"(b0), "r"(b1));
}

__device__ __forceinline__ uint32_t pack_bf16(float x, float y) {
    __nv_bfloat16 bx = __float2bfloat16(x), by = __float2bfloat16(y);
    return (uint32_t)__bfloat16_as_ushort(bx) |
           ((uint32_t)__bfloat16_as_ushort(by) << 16);
}

// ---------------------------------------------------------------------------
// Degree + histogram / normalization
// ---------------------------------------------------------------------------
__global__ void k_init_deg(int n) {
    int i = blockIdx.x * blockDim.x + threadIdx.x;
    if (i < n) { g_deg[i] = 1.0f; g_cnt[i] = 0; }
}
__global__ void k_deg_accum(const int* __restrict__ dst, const float* __restrict__ w, int E) {
    int e = blockIdx.x * blockDim.x + threadIdx.x;
    if (e < E) {
        int d = dst[e];
        atomicAdd(&g_deg[d], w[e]);
        atomicAdd(&g_cnt[d], 1);
    }
}
__global__ void k_dinv(int n) {
    int i = blockIdx.x * blockDim.x + threadIdx.x;
    if (i < n) {
        float d = g_deg[i];
        g_dinv[i] = (d > 0.0f) ? rsqrtf(d) : 0.0f;
    }
}

// Single-block exclusive scan over g_cnt -> g_off, g_cur. blockDim = 1024.
__global__ void k_scan(int n) {
    __shared__ int warp_sums[32];
    const int T = 1024;
    int tid = threadIdx.x;
    int per = (n + T - 1) / T;
    int beg = tid * per;
    int end = min(beg + per, n);
    int s = 0;
    for (int i = beg; i < end; i++) s += g_cnt[i];
    int lane = tid & 31, wid = tid >> 5;
    int v = s;
#pragma unroll
    for (int o = 1; o < 32; o <<= 1) {
        int t = __shfl_up_sync(0xFFFFFFFFu, v, o);
        if (lane >= o) v += t;
    }
    if (lane == 31) warp_sums[wid] = v;
    __syncthreads();
    if (wid == 0) {
        int wv = warp_sums[lane];
#pragma unroll
        for (int o = 1; o < 32; o <<= 1) {
            int t = __shfl_up_sync(0xFFFFFFFFu, wv, o);
            if (lane >= o) wv += t;
        }
        warp_sums[lane] = wv;
    }
    __syncthreads();
    int excl = v - s + (wid > 0 ? warp_sums[wid - 1] : 0);
    int run = excl;
    for (int i = beg; i < end; i++) {
        g_off[i] = run;
        g_cur[i] = run;
        run += g_cnt[i];
    }
    if (end == n) g_off[n] = run;
}

// Fill dst-binned edge list with precomputed coefficients
__global__ void k_fill(const int* __restrict__ src, const int* __restrict__ dst,
                       const float* __restrict__ w, int E) {
    int e = blockIdx.x * blockDim.x + threadIdx.x;
    if (e >= E) return;
    int s = src[e], d = dst[e];
    float coef = g_dinv[s] * __ldg(&w[e]) * g_dinv[d];
    int pos = atomicAdd(&g_cur[d], 1);
    g_edges[pos] = make_uint2((uint32_t)s, __float_as_uint(coef));
}

// Transposed weight split: W [K,N] row-major -> out [N,K] bf16 hi/lo
__global__ void k_split_wT(const float* __restrict__ W,
                           __nv_bfloat16* __restrict__ hiT,
                           __nv_bfloat16* __restrict__ loT, int K, int N) {
    int idx = blockIdx.x * blockDim.x + threadIdx.x;
    if (idx >= K * N) return;
    int n = idx / K, k = idx % K;
    float v = W[(size_t)k * N + n];
    __nv_bfloat16 h = __float2bfloat16(v);
    hiT[(size_t)n * K + k] = h;
    loT[(size_t)n * K + k] = __float2bfloat16(v - __bfloat162float(h));
}

// ---------------------------------------------------------------------------
// mma.sync bf16 split GEMM (same as round 3)
// ---------------------------------------------------------------------------
template <int MODE>
__global__ __launch_bounds__(256)
void mma_gemm(const float* __restrict__ A,
              const __nv_bfloat16* __restrict__ b_hi,
              const __nv_bfloat16* __restrict__ b_lo,
              const float* __restrict__ bias,
              float* __restrict__ outp,
              int M, int K) {
    extern __shared__ char smem[];
    constexpr int SM_AH = 0, SM_AL = 16384, SM_BH = 32768, SM_BL = 49152;

    uint32_t sbase = smem_to_u32(smem);
    int tid = threadIdx.x;
    int wid = tid >> 5, lane = tid & 31;
    int wm = wid & 3, wn = wid >> 2;
    int rowBase = blockIdx.y * 128;
    int colBase = blockIdx.x * 128;

    float acc[2][8][4];
#pragma unroll
    for (int i = 0; i < 2; i++)
#pragma unroll
        for (int j = 0; j < 8; j++)
#pragma unroll
            for (int k = 0; k < 4; k++) acc[i][j][k] = 0.0f;

    uint32_t lr = lane & 7, lg = lane >> 3;

    int nchunk = K >> 6;
    for (int c = 0; c < nchunk; c++) {
        int k0 = c << 6;
        for (int t = tid; t < 1024; t += 256) {
            int r = t >> 3, q = t & 7;
            int grow = rowBase + r;
            float4 v0 = make_float4(0.f, 0.f, 0.f, 0.f), v1 = v0;
            if (grow < M) {
                const float* ap = A + (size_t)grow * K + k0 + q * 8;
                v0 = *(const float4*)ap;
                v1 = *(const float4*)(ap + 4);
            }
            uint4 hi, lo;
            hi.x = pack_bf16(v0.x, v0.y); hi.y = pack_bf16(v0.z, v0.w);
            hi.z = pack_bf16(v1.x, v1.y); hi.w = pack_bf16(v1.z, v1.w);
            float r0 = v0.x - __bfloat162float(__ushort_as_bfloat16((unsigned short)(hi.x & 0xFFFF)));
            float r1 = v0.y - __bfloat162float(__ushort_as_bfloat16((unsigned short)(hi.x >> 16)));
            float r2 = v0.z - __bfloat162float(__ushort_as_bfloat16((unsigned short)(hi.y & 0xFFFF)));
            float r3 = v0.w - __bfloat162float(__ushort_as_bfloat16((unsigned short)(hi.y >> 16)));
            float r4 = v1.x - __bfloat162float(__ushort_as_bfloat16((unsigned short)(hi.z & 0xFFFF)));
            float r5 = v1.y - __bfloat162float(__ushort_as_bfloat16((unsigned short)(hi.z >> 16)));
            float r6 = v1.z - __bfloat162float(__ushort_as_bfloat16((unsigned short)(hi.w & 0xFFFF)));
            float r7 = v1.w - __bfloat162float(__ushort_as_bfloat16((unsigned short)(hi.w >> 16)));
            lo.x = pack_bf16(r0, r1); lo.y = pack_bf16(r2, r3);
            lo.z = pack_bf16(r4, r5); lo.w = pack_bf16(r6, r7);
            uint32_t sw = SMEM_SWIZZLE_128B((uint32_t)(r * 128 + q * 16));
            *(uint4*)(smem + SM_AH + sw) = hi;
            *(uint4*)(smem + SM_AL + sw) = lo;
        }
        for (int t = tid; t < 2048; t += 256) {
            int which = t >> 10;
            int r = (t >> 3) & 127, q = t & 7;
            const __nv_bfloat16* sp = which ? b_lo : b_hi;
            uint4 v = *(const uint4*)(sp + (size_t)(colBase + r) * K + k0 + q * 8);
            uint32_t sw = SMEM_SWIZZLE_128B((uint32_t)(r * 128 + q * 16));
            *(uint4*)(smem + (which ? SM_BL : SM_BH) + sw) = v;
        }
        __syncthreads();

#pragma unroll
        for (int s = 0; s < 4; s++) {
            uint32_t ah[2][4], al[2][4], bh[4][4], bl[4][4];
#pragma unroll
            for (int fm = 0; fm < 2; fm++) {
                uint32_t row = (uint32_t)(wm * 32 + fm * 16 + ((lg & 1) << 3) + lr);
                uint32_t kb = (uint32_t)(s * 32 + ((lg >> 1) << 4));
                uint32_t off = SMEM_SWIZZLE_128B(row * 128 + kb);
                ldsm_x4(ah[fm], sbase + SM_AH + off);
                ldsm_x4(al[fm], sbase + SM_AL + off);
            }
#pragma unroll
            for (int fn2 = 0; fn2 < 4; fn2++) {
                uint32_t row = (uint32_t)(wn * 64 + fn2 * 16 + ((lg >> 1) << 3) + lr);
                uint32_t kb = (uint32_t)(s * 32 + ((lg & 1) << 4));
                uint32_t off = SMEM_SWIZZLE_128B(row * 128 + kb);
                ldsm_x4(bh[fn2], sbase + SM_BH + off);
                ldsm_x4(bl[fn2], sbase + SM_BL + off);
            }
#pragma unroll
            for (int fm = 0; fm < 2; fm++)
#pragma unroll
                for (int fn2 = 0; fn2 < 4; fn2++)
#pragma unroll
                    for (int nh = 0; nh < 2; nh++) {
                        float* cc = acc[fm][fn2 * 2 + nh];
                        mma_bf16(cc, ah[fm], bh[fn2][nh * 2], bh[fn2][nh * 2 + 1]);
                        mma_bf16(cc, ah[fm], bl[fn2][nh * 2], bl[fn2][nh * 2 + 1]);
                        mma_bf16(cc, al[fm], bh[fn2][nh * 2], bh[fn2][nh * 2 + 1]);
                    }
        }
        __syncthreads();
    }

    int gq = lane >> 2;
    int tq = lane & 3;
#pragma unroll
    for (int fm = 0; fm < 2; fm++) {
#pragma unroll
        for (int half = 0; half < 2; half++) {
            int row = rowBase + wm * 32 + fm * 16 + half * 8 + gq;
            if (row >= M) continue;
            float sc = 0.0f;
            if (MODE == 0) { float di = g_dinv[row]; sc = di * di; }
#pragma unroll
            for (int fn = 0; fn < 8; fn++) {
                int col = colBase + wn * 64 + fn * 8 + tq * 2;
                float c0 = acc[fm][fn][half * 2 + 0];
                float c1 = acc[fm][fn][half * 2 + 1];
                if (MODE == 0) {
                    *(float2*)(g_h + (size_t)row * 128 + col) = make_float2(c0, c1);
                    float b0 = __ldg(bias + col), b1 = __ldg(bias + col + 1);
                    *(float2*)(g_agg + (size_t)row * 128 + col) =
                        make_float2(fmaf(c0, sc, b0), fmaf(c1, sc, b1));
                } else {
                    float b0 = __ldg(bias + col), b1 = __ldg(bias + col + 1);
                    *(float2*)(outp + (size_t)row * 512 + col) = make_float2(c0 + b0, c1 + b1);
                }
            }
        }
    }
}

// ---------------------------------------------------------------------------
// Gather-aggregate: one warp per dst node, no atomics.
// acc initialized from g_agg (self-loop + bias, written by GEMM1 epilogue).
// ---------------------------------------------------------------------------
__global__ __launch_bounds__(256)
void k_gather(int n) {
    int gwarp = (blockIdx.x * blockDim.x + threadIdx.x) >> 5;
    int lane = threadIdx.x & 31;
    if (gwarp >= n) return;
    int d = gwarp;
    int beg = g_off[d], end = g_off[d + 1];

    float4 acc = *(const float4*)(g_agg + (size_t)d * H_DIM + lane * 4);

    for (int base = beg; base < end; base += 32) {
        int idx = base + lane;
        uint2 e = (idx < end) ? g_edges[idx] : make_uint2(0u, 0u);
        int cnt = min(32, end - base);
#pragma unroll 4
        for (int j = 0; j < cnt; j++) {
            int s = __shfl_sync(0xFFFFFFFFu, (int)e.x, j);
            float cf = __shfl_sync(0xFFFFFFFFu, __uint_as_float(e.y), j);
            float4 hv = *(const float4*)(g_h + (size_t)s * H_DIM + lane * 4);
            acc.x = fmaf(cf, hv.x, acc.x);
            acc.y = fmaf(cf, hv.y, acc.y);
            acc.z = fmaf(cf, hv.z, acc.z);
            acc.w = fmaf(cf, hv.w, acc.w);
        }
    }
    *(float4*)(g_agg + (size_t)d * H_DIM + lane * 4) = acc;
}

// ---------------------------------------------------------------------------
extern "C" void kernel_launch(void* const* d_in, const int* in_sizes, int n_in,
                              void* d_out, int out_size) {
    const float* x  = (const float*)d_in[0];
    const int*   ei = (const int*)  d_in[1];
    const float* ew = (const float*)d_in[2];
    const float* Wc = (const float*)d_in[3];  // [512,128]
    const float* bc = (const float*)d_in[4];
    const float* Wl = (const float*)d_in[5];  // [128,512]
    const float* bl = (const float*)d_in[6];
    float* out = (float*)d_out;

    int E = in_sizes[2];
    int n = in_sizes[0] / F_INF;
    const int* src = ei;
    const int* dst = ei + E;

    const int SMEM_BYTES = 65536;
    cudaFuncSetAttribute(mma_gemm<0>, cudaFuncAttributeMaxDynamicSharedMemorySize, SMEM_BYTES);
    cudaFuncSetAttribute(mma_gemm<1>, cudaFuncAttributeMaxDynamicSharedMemorySize, SMEM_BYTES);

    __nv_bfloat16 *wch, *wcl, *wlh, *wll;
    float *dagg;
    cudaGetSymbolAddress((void**)&wch, g_wch);
    cudaGetSymbolAddress((void**)&wcl, g_wcl);
    cudaGetSymbolAddress((void**)&wlh, g_wlh);
    cudaGetSymbolAddress((void**)&wll, g_wll);
    cudaGetSymbolAddress((void**)&dagg, g_agg);

    // 1) degree + histogram + norm
    k_init_deg<<<(n + 255) / 256, 256>>>(n);
    k_deg_accum<<<(E + 255) / 256, 256>>>(dst, ew, E);
    k_dinv<<<(n + 255) / 256, 256>>>(n);

    // 2) bin edges by dst
    k_scan<<<1, 1024>>>(n);
    k_fill<<<(E + 255) / 256, 256>>>(src, dst, ew, E);

    // 3) weight splits
    k_split_wT<<<(F_INF * H_DIM + 255) / 256, 256>>>(Wc, wch, wcl, F_INF, H_DIM);
    k_split_wT<<<(F_INF * H_DIM + 255) / 256, 256>>>(Wl, wlh, wll, H_DIM, F_INF);

    // 4) GEMM1: h = x @ Wc ; agg = h*dinv^2 + b_conv
    {
        dim3 grid(1, (n + 127) / 128);
        mma_gemm<0><<<grid, 256, SMEM_BYTES>>>(x, wch, wcl, bc, nullptr, n, F_INF);
    }

    // 5) gather-aggregate (atomic-free)
    {
        int blocks = (n * 32 + 255) / 256;
        k_gather<<<blocks, 256>>>(n);
    }

    // 6) GEMM2: out = agg @ Wl + b_lin
    {
        dim3 grid(F_INF / 128, (n + 127) / 128);
        mma_gemm<1><<<grid, 256, SMEM_BYTES>>>(dagg, wlh, wll, bl, out, n, H_DIM);
    }
}

// round 5
// speedup vs baseline: 1.7115x; 1.1894x over previous
#include <cuda_runtime.h>
#include <cuda_bf16.h>
#include <cstdint>

#define N_NODES 50000
#define F_INF   512
#define H_DIM   128
#define E_MAX   1600000

// ---------------------------------------------------------------------------
// Device scratch (allocation-free rule: device globals)
// ---------------------------------------------------------------------------
__device__ float g_deg [N_NODES];
__device__ float g_dinv[N_NODES];
__device__ int   g_cnt [N_NODES];
__device__ int   g_off [N_NODES];
__device__ int   g_cur [N_NODES];
__device__ int   g_total;
__device__ __align__(16) uint2 g_edges[E_MAX];                   // (src, coef) 12.8 MB
__device__ __align__(16) float g_h   [(size_t)N_NODES * H_DIM];  // 25.6 MB
__device__ __align__(16) float g_agg [(size_t)N_NODES * H_DIM];  // 25.6 MB
__device__ __align__(16) __nv_bfloat16 g_wch [H_DIM * F_INF];
__device__ __align__(16) __nv_bfloat16 g_wcl [H_DIM * F_INF];
__device__ __align__(16) __nv_bfloat16 g_wlh [F_INF * H_DIM];
__device__ __align__(16) __nv_bfloat16 g_wll [F_INF * H_DIM];

#define SMEM_SWIZZLE_128B(off) ((off) ^ (((off) >> 3) & 0x70))

__device__ __forceinline__ uint32_t smem_to_u32(const void* p) {
    uint32_t a;
    asm("{ .reg .u64 t; cvta.to.shared.u64 t, %1; cvt.u32.u64 %0, t; }"
        : "=r"(a) : "l"(p));
    return a;
}

__device__ __forceinline__ void ldsm_x4(uint32_t* r, uint32_t addr) {
    asm volatile("ldmatrix.sync.aligned.m8n8.x4.shared.b16 {%0,%1,%2,%3}, [%4];"
                 : "=r"(r[0]), "=r"(r[1]), "=r"(r[2]), "=r"(r[3]) : "r"(addr));
}

__device__ __forceinline__ void mma_bf16(float* c, const uint32_t* a,
                                         uint32_t b0, uint32_t b1) {
    asm volatile(
        "mma.sync.aligned.m16n8k16.row.col.f32.bf16.bf16.f32 "
        "{%0,%1,%2,%3}, {%4,%5,%6,%7}, {%8,%9}, {%0,%1,%2,%3};"
        : "+f"(c[0]), "+f"(c[1]), "+f"(c[2]), "+f"(c[3])
        : "r"(a[0]), "r"(a[1]), "r"(a[2]), "r"(a[3]), "r"(b0), "r"(b1));
}

__device__ __forceinline__ uint32_t pack_bf16(float x, float y) {
    __nv_bfloat16 bx = __float2bfloat16(x), by = __float2bfloat16(y);
    return (uint32_t)__bfloat16_as_ushort(bx) |
           ((uint32_t)__bfloat16_as_ushort(by) << 16);
}

// ---------------------------------------------------------------------------
// Degree + histogram / normalization
// ---------------------------------------------------------------------------
__global__ void k_init_deg(int n) {
    int i = blockIdx.x * blockDim.x + threadIdx.x;
    if (i < n) { g_deg[i] = 1.0f; g_cnt[i] = 0; }
    if (i == 0) g_total = 0;
}
__global__ void k_deg_accum(const int* __restrict__ dst, const float* __restrict__ w, int E) {
    int e = blockIdx.x * blockDim.x + threadIdx.x;
    if (e < E) {
        int d = dst[e];
        atomicAdd(&g_deg[d], w[e]);
        atomicAdd(&g_cnt[d], 1);
    }
}

// dinv + warp-aggregated bin-range assignment (order-free replacement for scan)
__global__ void k_dinv_assign(int n) {
    int i = blockIdx.x * blockDim.x + threadIdx.x;
    int lane = threadIdx.x & 31;
    float dg = 0.0f;
    int c = 0;
    if (i < n) {
        dg = g_deg[i];
        g_dinv[i] = (dg > 0.0f) ? rsqrtf(dg) : 0.0f;
        c = g_cnt[i];
    }
    // warp inclusive scan of c
    int v = c;
#pragma unroll
    for (int o = 1; o < 32; o <<= 1) {
        int t = __shfl_up_sync(0xFFFFFFFFu, v, o);
        if (lane >= o) v += t;
    }
    int warpTotal = __shfl_sync(0xFFFFFFFFu, v, 31);
    int base = 0;
    if (lane == 31 && warpTotal > 0) base = atomicAdd(&g_total, warpTotal);
    base = __shfl_sync(0xFFFFFFFFu, base, 31);
    if (i < n) {
        int off = base + v - c;   // exclusive prefix within warp
        g_off[i] = off;
        g_cur[i] = off;
    }
}

// Fill dst-binned edge list with precomputed coefficients
__global__ void k_fill(const int* __restrict__ src, const int* __restrict__ dst,
                       const float* __restrict__ w, int E) {
    int e = blockIdx.x * blockDim.x + threadIdx.x;
    if (e >= E) return;
    int s = src[e], d = dst[e];
    float coef = g_dinv[s] * __ldg(&w[e]) * g_dinv[d];
    int pos = atomicAdd(&g_cur[d], 1);
    g_edges[pos] = make_uint2((uint32_t)s, __float_as_uint(coef));
}

// Transposed weight split: W [K,N] row-major -> out [N,K] bf16 hi/lo
__global__ void k_split_wT(const float* __restrict__ W,
                           __nv_bfloat16* __restrict__ hiT,
                           __nv_bfloat16* __restrict__ loT, int K, int N) {
    int idx = blockIdx.x * blockDim.x + threadIdx.x;
    if (idx >= K * N) return;
    int n = idx / K, k = idx % K;
    float v = W[(size_t)k * N + n];
    __nv_bfloat16 h = __float2bfloat16(v);
    hiT[(size_t)n * K + k] = h;
    loT[(size_t)n * K + k] = __float2bfloat16(v - __bfloat162float(h));
}

// ---------------------------------------------------------------------------
// mma.sync bf16 split GEMM
// ---------------------------------------------------------------------------
template <int MODE>
__global__ __launch_bounds__(256)
void mma_gemm(const float* __restrict__ A,
              const __nv_bfloat16* __restrict__ b_hi,
              const __nv_bfloat16* __restrict__ b_lo,
              const float* __restrict__ bias,
              float* __restrict__ outp,
              int M, int K) {
    extern __shared__ char smem[];
    constexpr int SM_AH = 0, SM_AL = 16384, SM_BH = 32768, SM_BL = 49152;

    uint32_t sbase = smem_to_u32(smem);
    int tid = threadIdx.x;
    int wid = tid >> 5, lane = tid & 31;
    int wm = wid & 3, wn = wid >> 2;
    int rowBase = blockIdx.y * 128;
    int colBase = blockIdx.x * 128;

    float acc[2][8][4];
#pragma unroll
    for (int i = 0; i < 2; i++)
#pragma unroll
        for (int j = 0; j < 8; j++)
#pragma unroll
            for (int k = 0; k < 4; k++) acc[i][j][k] = 0.0f;

    uint32_t lr = lane & 7, lg = lane >> 3;

    int nchunk = K >> 6;
    for (int c = 0; c < nchunk; c++) {
        int k0 = c << 6;
        for (int t = tid; t < 1024; t += 256) {
            int r = t >> 3, q = t & 7;
            int grow = rowBase + r;
            float4 v0 = make_float4(0.f, 0.f, 0.f, 0.f), v1 = v0;
            if (grow < M) {
                const float* ap = A + (size_t)grow * K + k0 + q * 8;
                v0 = *(const float4*)ap;
                v1 = *(const float4*)(ap + 4);
            }
            uint4 hi, lo;
            hi.x = pack_bf16(v0.x, v0.y); hi.y = pack_bf16(v0.z, v0.w);
            hi.z = pack_bf16(v1.x, v1.y); hi.w = pack_bf16(v1.z, v1.w);
            float r0 = v0.x - __bfloat162float(__ushort_as_bfloat16((unsigned short)(hi.x & 0xFFFF)));
            float r1 = v0.y - __bfloat162float(__ushort_as_bfloat16((unsigned short)(hi.x >> 16)));
            float r2 = v0.z - __bfloat162float(__ushort_as_bfloat16((unsigned short)(hi.y & 0xFFFF)));
            float r3 = v0.w - __bfloat162float(__ushort_as_bfloat16((unsigned short)(hi.y >> 16)));
            float r4 = v1.x - __bfloat162float(__ushort_as_bfloat16((unsigned short)(hi.z & 0xFFFF)));
            float r5 = v1.y - __bfloat162float(__ushort_as_bfloat16((unsigned short)(hi.z >> 16)));
            float r6 = v1.z - __bfloat162float(__ushort_as_bfloat16((unsigned short)(hi.w & 0xFFFF)));
            float r7 = v1.w - __bfloat162float(__ushort_as_bfloat16((unsigned short)(hi.w >> 16)));
            lo.x = pack_bf16(r0, r1); lo.y = pack_bf16(r2, r3);
            lo.z = pack_bf16(r4, r5); lo.w = pack_bf16(r6, r7);
            uint32_t sw = SMEM_SWIZZLE_128B((uint32_t)(r * 128 + q * 16));
            *(uint4*)(smem + SM_AH + sw) = hi;
            *(uint4*)(smem + SM_AL + sw) = lo;
        }
        for (int t = tid; t < 2048; t += 256) {
            int which = t >> 10;
            int r = (t >> 3) & 127, q = t & 7;
            const __nv_bfloat16* sp = which ? b_lo : b_hi;
            uint4 v = *(const uint4*)(sp + (size_t)(colBase + r) * K + k0 + q * 8);
            uint32_t sw = SMEM_SWIZZLE_128B((uint32_t)(r * 128 + q * 16));
            *(uint4*)(smem + (which ? SM_BL : SM_BH) + sw) = v;
        }
        __syncthreads();

#pragma unroll
        for (int s = 0; s < 4; s++) {
            uint32_t ah[2][4], al[2][4], bh[4][4], bl[4][4];
#pragma unroll
            for (int fm = 0; fm < 2; fm++) {
                uint32_t row = (uint32_t)(wm * 32 + fm * 16 + ((lg & 1) << 3) + lr);
                uint32_t kb = (uint32_t)(s * 32 + ((lg >> 1) << 4));
                uint32_t off = SMEM_SWIZZLE_128B(row * 128 + kb);
                ldsm_x4(ah[fm], sbase + SM_AH + off);
                ldsm_x4(al[fm], sbase + SM_AL + off);
            }
#pragma unroll
            for (int fn2 = 0; fn2 < 4; fn2++) {
                uint32_t row = (uint32_t)(wn * 64 + fn2 * 16 + ((lg >> 1) << 3) + lr);
                uint32_t kb = (uint32_t)(s * 32 + ((lg & 1) << 4));
                uint32_t off = SMEM_SWIZZLE_128B(row * 128 + kb);
                ldsm_x4(bh[fn2], sbase + SM_BH + off);
                ldsm_x4(bl[fn2], sbase + SM_BL + off);
            }
#pragma unroll
            for (int fm = 0; fm < 2; fm++)
#pragma unroll
                for (int fn2 = 0; fn2 < 4; fn2++)
#pragma unroll
                    for (int nh = 0; nh < 2; nh++) {
                        float* cc = acc[fm][fn2 * 2 + nh];
                        mma_bf16(cc, ah[fm], bh[fn2][nh * 2], bh[fn2][nh * 2 + 1]);
                        mma_bf16(cc, ah[fm], bl[fn2][nh * 2], bl[fn2][nh * 2 + 1]);
                        mma_bf16(cc, al[fm], bh[fn2][nh * 2], bh[fn2][nh * 2 + 1]);
                    }
        }
        __syncthreads();
    }

    int gq = lane >> 2;
    int tq = lane & 3;
#pragma unroll
    for (int fm = 0; fm < 2; fm++) {
#pragma unroll
        for (int half = 0; half < 2; half++) {
            int row = rowBase + wm * 32 + fm * 16 + half * 8 + gq;
            if (row >= M) continue;
            float sc = 0.0f;
            if (MODE == 0) { float di = g_dinv[row]; sc = di * di; }
#pragma unroll
            for (int fn = 0; fn < 8; fn++) {
                int col = colBase + wn * 64 + fn * 8 + tq * 2;
                float c0 = acc[fm][fn][half * 2 + 0];
                float c1 = acc[fm][fn][half * 2 + 1];
                if (MODE == 0) {
                    *(float2*)(g_h + (size_t)row * 128 + col) = make_float2(c0, c1);
                    float b0 = __ldg(bias + col), b1 = __ldg(bias + col + 1);
                    *(float2*)(g_agg + (size_t)row * 128 + col) =
                        make_float2(fmaf(c0, sc, b0), fmaf(c1, sc, b1));
                } else {
                    float b0 = __ldg(bias + col), b1 = __ldg(bias + col + 1);
                    *(float2*)(outp + (size_t)row * 512 + col) = make_float2(c0 + b0, c1 + b1);
                }
            }
        }
    }
}

// ---------------------------------------------------------------------------
// Gather-aggregate: one warp per dst node, no atomics.
// ---------------------------------------------------------------------------
__global__ __launch_bounds__(256)
void k_gather(int n) {
    int gwarp = (blockIdx.x * blockDim.x + threadIdx.x) >> 5;
    int lane = threadIdx.x & 31;
    if (gwarp >= n) return;
    int d = gwarp;
    int beg = g_off[d];
    int end = beg + g_cnt[d];

    float4 acc = *(const float4*)(g_agg + (size_t)d * H_DIM + lane * 4);

    for (int base = beg; base < end; base += 32) {
        int idx = base + lane;
        uint2 e = (idx < end) ? g_edges[idx] : make_uint2(0u, 0u);
        int cnt = min(32, end - base);
#pragma unroll 4
        for (int j = 0; j < cnt; j++) {
            int s = __shfl_sync(0xFFFFFFFFu, (int)e.x, j);
            float cf = __shfl_sync(0xFFFFFFFFu, __uint_as_float(e.y), j);
            float4 hv = *(const float4*)(g_h + (size_t)s * H_DIM + lane * 4);
            acc.x = fmaf(cf, hv.x, acc.x);
            acc.y = fmaf(cf, hv.y, acc.y);
            acc.z = fmaf(cf, hv.z, acc.z);
            acc.w = fmaf(cf, hv.w, acc.w);
        }
    }
    *(float4*)(g_agg + (size_t)d * H_DIM + lane * 4) = acc;
}

// ---------------------------------------------------------------------------
extern "C" void kernel_launch(void* const* d_in, const int* in_sizes, int n_in,
                              void* d_out, int out_size) {
    const float* x  = (const float*)d_in[0];
    const int*   ei = (const int*)  d_in[1];
    const float* ew = (const float*)d_in[2];
    const float* Wc = (const float*)d_in[3];  // [512,128]
    const float* bc = (const float*)d_in[4];
    const float* Wl = (const float*)d_in[5];  // [128,512]
    const float* bl = (const float*)d_in[6];
    float* out = (float*)d_out;

    int E = in_sizes[2];
    int n = in_sizes[0] / F_INF;
    const int* src = ei;
    const int* dst = ei + E;

    const int SMEM_BYTES = 65536;
    cudaFuncSetAttribute(mma_gemm<0>, cudaFuncAttributeMaxDynamicSharedMemorySize, SMEM_BYTES);
    cudaFuncSetAttribute(mma_gemm<1>, cudaFuncAttributeMaxDynamicSharedMemorySize, SMEM_BYTES);

    __nv_bfloat16 *wch, *wcl, *wlh, *wll;
    float *dagg;
    cudaGetSymbolAddress((void**)&wch, g_wch);
    cudaGetSymbolAddress((void**)&wcl, g_wcl);
    cudaGetSymbolAddress((void**)&wlh, g_wlh);
    cudaGetSymbolAddress((void**)&wll, g_wll);
    cudaGetSymbolAddress((void**)&dagg, g_agg);

    // 1) degree + histogram
    k_init_deg<<<(n + 255) / 256, 256>>>(n);
    k_deg_accum<<<(E + 255) / 256, 256>>>(dst, ew, E);

    // 2) dinv + bin-range assignment (no scan), then fill bins
    k_dinv_assign<<<(n + 255) / 256, 256>>>(n);
    k_fill<<<(E + 255) / 256, 256>>>(src, dst, ew, E);

    // 3) weight splits
    k_split_wT<<<(F_INF * H_DIM + 255) / 256, 256>>>(Wc, wch, wcl, F_INF, H_DIM);
    k_split_wT<<<(F_INF * H_DIM + 255) / 256, 256>>>(Wl, wlh, wll, H_DIM, F_INF);

    // 4) GEMM1: h = x @ Wc ; agg = h*dinv^2 + b_conv
    {
        dim3 grid(1, (n + 127) / 128);
        mma_gemm<0><<<grid, 256, SMEM_BYTES>>>(x, wch, wcl, bc, nullptr, n, F_INF);
    }

    // 5) gather-aggregate (atomic-free)
    {
        int blocks = (n * 32 + 255) / 256;
        k_gather<<<blocks, 256>>>(n);
    }

    // 6) GEMM2: out = agg @ Wl + b_lin
    {
        dim3 grid(F_INF / 128, (n + 127) / 128);
        mma_gemm<1><<<grid, 256, SMEM_BYTES>>>(dagg, wlh, wll, bl, out, n, H_DIM);
    }
}

// round 6
// speedup vs baseline: 2.3306x; 1.3617x over previous
#include <cuda_runtime.h>
#include <cuda_bf16.h>
#include <cstdint>

#define N_NODES 50000
#define F_INF   512
#define H_DIM   128
#define E_MAX   1600000

// ---------------------------------------------------------------------------
// Device scratch (allocation-free rule: device globals)
// ---------------------------------------------------------------------------
__device__ float g_deg [N_NODES];
__device__ float g_dinv[N_NODES];
__device__ int   g_cnt [N_NODES];
__device__ int   g_off [N_NODES];
__device__ int   g_cur [N_NODES];
__device__ int   g_total;
__device__ __align__(16) uint2 g_edges[E_MAX];                   // (src, coef) 12.8 MB
__device__ __align__(16) float g_h   [(size_t)N_NODES * H_DIM];  // 25.6 MB
__device__ __align__(16) float g_agg [(size_t)N_NODES * H_DIM];  // 25.6 MB
__device__ __align__(16) __nv_bfloat16 g_wch [H_DIM * F_INF];
__device__ __align__(16) __nv_bfloat16 g_wcl [H_DIM * F_INF];
__device__ __align__(16) __nv_bfloat16 g_wlh [F_INF * H_DIM];
__device__ __align__(16) __nv_bfloat16 g_wll [F_INF * H_DIM];

#define SMEM_SWIZZLE_128B(off) ((off) ^ (((off) >> 3) & 0x70))

__device__ __forceinline__ uint32_t smem_to_u32(const void* p) {
    uint32_t a;
    asm("{ .reg .u64 t; cvta.to.shared.u64 t, %1; cvt.u32.u64 %0, t; }"
        : "=r"(a) : "l"(p));
    return a;
}

__device__ __forceinline__ void ldsm_x4(uint32_t* r, uint32_t addr) {
    asm volatile("ldmatrix.sync.aligned.m8n8.x4.shared.b16 {%0,%1,%2,%3}, [%4];"
                 : "=r"(r[0]), "=r"(r[1]), "=r"(r[2]), "=r"(r[3]) : "r"(addr));
}

__device__ __forceinline__ void mma_bf16(float* c, const uint32_t* a,
                                         uint32_t b0, uint32_t b1) {
    asm volatile(
        "mma.sync.aligned.m16n8k16.row.col.f32.bf16.bf16.f32 "
        "{%0,%1,%2,%3}, {%4,%5,%6,%7}, {%8,%9}, {%0,%1,%2,%3};"
        : "+f"(c[0]), "+f"(c[1]), "+f"(c[2]), "+f"(c[3])
        : "r"(a[0]), "r"(a[1]), "r"(a[2]), "r"(a[3]), "r"(b0), "r"(b1));
}

__device__ __forceinline__ uint32_t pack_bf16(float x, float y) {
    __nv_bfloat16 bx = __float2bfloat16(x), by = __float2bfloat16(y);
    return (uint32_t)__bfloat16_as_ushort(bx) |
           ((uint32_t)__bfloat16_as_ushort(by) << 16);
}

__device__ __forceinline__ void cp_async16(uint32_t smem_addr, const void* gptr) {
    asm volatile("cp.async.cg.shared.global [%0], [%1], 16;"
                 :: "r"(smem_addr), "l"(gptr));
}

// ---------------------------------------------------------------------------
// Degree + histogram / normalization
// ---------------------------------------------------------------------------
__global__ void k_init_deg(int n) {
    int i = blockIdx.x * blockDim.x + threadIdx.x;
    if (i < n) { g_deg[i] = 1.0f; g_cnt[i] = 0; }
    if (i == 0) g_total = 0;
}
__global__ void k_deg_accum(const int* __restrict__ dst, const float* __restrict__ w, int E) {
    int e = blockIdx.x * blockDim.x + threadIdx.x;
    if (e < E) {
        int d = dst[e];
        atomicAdd(&g_deg[d], w[e]);
        atomicAdd(&g_cnt[d], 1);
    }
}

// dinv + warp-aggregated bin-range assignment (order-free)
__global__ void k_dinv_assign(int n) {
    int i = blockIdx.x * blockDim.x + threadIdx.x;
    int lane = threadIdx.x & 31;
    float dg = 0.0f;
    int c = 0;
    if (i < n) {
        dg = g_deg[i];
        g_dinv[i] = (dg > 0.0f) ? rsqrtf(dg) : 0.0f;
        c = g_cnt[i];
    }
    int v = c;
#pragma unroll
    for (int o = 1; o < 32; o <<= 1) {
        int t = __shfl_up_sync(0xFFFFFFFFu, v, o);
        if (lane >= o) v += t;
    }
    int warpTotal = __shfl_sync(0xFFFFFFFFu, v, 31);
    int base = 0;
    if (lane == 31 && warpTotal > 0) base = atomicAdd(&g_total, warpTotal);
    base = __shfl_sync(0xFFFFFFFFu, base, 31);
    if (i < n) {
        int off = base + v - c;
        g_off[i] = off;
        g_cur[i] = off;
    }
}

// Fill dst-binned edge list with precomputed coefficients
__global__ void k_fill(const int* __restrict__ src, const int* __restrict__ dst,
                       const float* __restrict__ w, int E) {
    int e = blockIdx.x * blockDim.x + threadIdx.x;
    if (e >= E) return;
    int s = src[e], d = dst[e];
    float coef = g_dinv[s] * __ldg(&w[e]) * g_dinv[d];
    int pos = atomicAdd(&g_cur[d], 1);
    g_edges[pos] = make_uint2((uint32_t)s, __float_as_uint(coef));
}

// Transposed weight split: W [K,N] row-major -> out [N,K] bf16 hi/lo
__global__ void k_split_wT(const float* __restrict__ W,
                           __nv_bfloat16* __restrict__ hiT,
                           __nv_bfloat16* __restrict__ loT, int K, int N) {
    int idx = blockIdx.x * blockDim.x + threadIdx.x;
    if (idx >= K * N) return;
    int n = idx / K, k = idx % K;
    float v = W[(size_t)k * N + n];
    __nv_bfloat16 h = __float2bfloat16(v);
    hiT[(size_t)n * K + k] = h;
    loT[(size_t)n * K + k] = __float2bfloat16(v - __bfloat162float(h));
}

// ---------------------------------------------------------------------------
// Pipelined mma.sync bf16-split GEMM.
//   A: fp32 gmem, prefetched one chunk ahead into registers, converted on STS.
//   B: bf16 hi/lo gmem, cp.async into double-buffered smem.
// MODE 0: A = x [M,512], B = WcT -> writes g_h only
// MODE 1: A = g_agg [M,128], B = WlT -> writes out + b_lin
// ---------------------------------------------------------------------------
template <int MODE>
__global__ __launch_bounds__(256)
void mma_gemm(const float* __restrict__ A,
              const __nv_bfloat16* __restrict__ b_hi,
              const __nv_bfloat16* __restrict__ b_lo,
              const float* __restrict__ bias,
              float* __restrict__ outp,
              int M, int K) {
    extern __shared__ char smem[];
    constexpr int SM_AH = 0, SM_AL = 16384;
    constexpr int SM_B0 = 32768, SM_B1 = 65536;   // each: hi +0, lo +16384

    uint32_t sbase = smem_to_u32(smem);
    int tid = threadIdx.x;
    int wid = tid >> 5, lane = tid & 31;
    int wm = wid & 3, wn = wid >> 2;
    int rowBase = blockIdx.y * 128;
    int colBase = blockIdx.x * 128;

    float acc[2][8][4];
#pragma unroll
    for (int i = 0; i < 2; i++)
#pragma unroll
        for (int j = 0; j < 8; j++)
#pragma unroll
            for (int k = 0; k < 4; k++) acc[i][j][k] = 0.0f;

    uint32_t lr = lane & 7, lg = lane >> 3;
    int nchunk = K >> 6;

    // ---- prefetch helpers ----
    float4 aR[4][2];
    auto ldA = [&](int c) {
        int k0 = c << 6;
#pragma unroll
        for (int l = 0; l < 4; l++) {
            int t = tid + l * 256;
            int r = t >> 3, q = t & 7;
            int grow = rowBase + r;
            float4 v0 = make_float4(0.f, 0.f, 0.f, 0.f), v1 = v0;
            if (grow < M) {
                const float* ap = A + (size_t)grow * K + k0 + q * 8;
                v0 = *(const float4*)ap;
                v1 = *(const float4*)(ap + 4);
            }
            aR[l][0] = v0; aR[l][1] = v1;
        }
    };
    auto stsA = [&]() {
#pragma unroll
        for (int l = 0; l < 4; l++) {
            int t = tid + l * 256;
            int r = t >> 3, q = t & 7;
            float4 v0 = aR[l][0], v1 = aR[l][1];
            uint4 hi, lo;
            hi.x = pack_bf16(v0.x, v0.y); hi.y = pack_bf16(v0.z, v0.w);
            hi.z = pack_bf16(v1.x, v1.y); hi.w = pack_bf16(v1.z, v1.w);
            float r0 = v0.x - __bfloat162float(__ushort_as_bfloat16((unsigned short)(hi.x & 0xFFFF)));
            float r1 = v0.y - __bfloat162float(__ushort_as_bfloat16((unsigned short)(hi.x >> 16)));
            float r2 = v0.z - __bfloat162float(__ushort_as_bfloat16((unsigned short)(hi.y & 0xFFFF)));
            float r3 = v0.w - __bfloat162float(__ushort_as_bfloat16((unsigned short)(hi.y >> 16)));
            float r4 = v1.x - __bfloat162float(__ushort_as_bfloat16((unsigned short)(hi.z & 0xFFFF)));
            float r5 = v1.y - __bfloat162float(__ushort_as_bfloat16((unsigned short)(hi.z >> 16)));
            float r6 = v1.z - __bfloat162float(__ushort_as_bfloat16((unsigned short)(hi.w & 0xFFFF)));
            float r7 = v1.w - __bfloat162float(__ushort_as_bfloat16((unsigned short)(hi.w >> 16)));
            lo.x = pack_bf16(r0, r1); lo.y = pack_bf16(r2, r3);
            lo.z = pack_bf16(r4, r5); lo.w = pack_bf16(r6, r7);
            uint32_t sw = SMEM_SWIZZLE_128B((uint32_t)(r * 128 + q * 16));
            *(uint4*)(smem + SM_AH + sw) = hi;
            *(uint4*)(smem + SM_AL + sw) = lo;
        }
    };
    auto cpB = [&](int c, int buf) {
        int k0 = c << 6;
        int bb = buf ? SM_B1 : SM_B0;
#pragma unroll
        for (int l = 0; l < 8; l++) {
            int t = tid + l * 256;
            int which = t >> 10;
            int r = (t >> 3) & 127, q = t & 7;
            const __nv_bfloat16* sp = which ? b_lo : b_hi;
            const void* gp = sp + (size_t)(colBase + r) * K + k0 + q * 8;
            uint32_t sw = SMEM_SWIZZLE_128B((uint32_t)(r * 128 + q * 16));
            cp_async16(sbase + bb + which * 16384 + sw, gp);
        }
        asm volatile("cp.async.commit_group;" ::: "memory");
    };

    // ---- pipeline prologue ----
    ldA(0);
    cpB(0, 0);

    for (int c = 0; c < nchunk; c++) {
        int buf = c & 1;
        stsA();
        asm volatile("cp.async.wait_group 0;" ::: "memory");
        __syncthreads();
        if (c + 1 < nchunk) { ldA(c + 1); cpB(c + 1, buf ^ 1); }

        int BH = (buf ? SM_B1 : SM_B0);
        int BL = BH + 16384;
#pragma unroll
        for (int s = 0; s < 4; s++) {
            uint32_t ah[2][4], al[2][4], bh[4][4], bl[4][4];
#pragma unroll
            for (int fm = 0; fm < 2; fm++) {
                uint32_t row = (uint32_t)(wm * 32 + fm * 16 + ((lg & 1) << 3) + lr);
                uint32_t kb = (uint32_t)(s * 32 + ((lg >> 1) << 4));
                uint32_t off = SMEM_SWIZZLE_128B(row * 128 + kb);
                ldsm_x4(ah[fm], sbase + SM_AH + off);
                ldsm_x4(al[fm], sbase + SM_AL + off);
            }
#pragma unroll
            for (int fn2 = 0; fn2 < 4; fn2++) {
                uint32_t row = (uint32_t)(wn * 64 + fn2 * 16 + ((lg >> 1) << 3) + lr);
                uint32_t kb = (uint32_t)(s * 32 + ((lg & 1) << 4));
                uint32_t off = SMEM_SWIZZLE_128B(row * 128 + kb);
                ldsm_x4(bh[fn2], sbase + BH + off);
                ldsm_x4(bl[fn2], sbase + BL + off);
            }
#pragma unroll
            for (int fm = 0; fm < 2; fm++)
#pragma unroll
                for (int fn2 = 0; fn2 < 4; fn2++)
#pragma unroll
                    for (int nh = 0; nh < 2; nh++) {
                        float* cc = acc[fm][fn2 * 2 + nh];
                        mma_bf16(cc, ah[fm], bh[fn2][nh * 2], bh[fn2][nh * 2 + 1]);
                        mma_bf16(cc, ah[fm], bl[fn2][nh * 2], bl[fn2][nh * 2 + 1]);
                        mma_bf16(cc, al[fm], bh[fn2][nh * 2], bh[fn2][nh * 2 + 1]);
                    }
        }
        __syncthreads();
    }

    // ---- Epilogue ----
    int gq = lane >> 2;
    int tq = lane & 3;
#pragma unroll
    for (int fm = 0; fm < 2; fm++) {
#pragma unroll
        for (int half = 0; half < 2; half++) {
            int row = rowBase + wm * 32 + fm * 16 + half * 8 + gq;
            if (row >= M) continue;
#pragma unroll
            for (int fn = 0; fn < 8; fn++) {
                int col = colBase + wn * 64 + fn * 8 + tq * 2;
                float c0 = acc[fm][fn][half * 2 + 0];
                float c1 = acc[fm][fn][half * 2 + 1];
                if (MODE == 0) {
                    *(float2*)(g_h + (size_t)row * 128 + col) = make_float2(c0, c1);
                } else {
                    float b0 = __ldg(bias + col), b1 = __ldg(bias + col + 1);
                    *(float2*)(outp + (size_t)row * 512 + col) = make_float2(c0 + b0, c1 + b1);
                }
            }
        }
    }
}

// ---------------------------------------------------------------------------
// Gather-aggregate: one warp per dst node, no atomics, MLP-8 batched loads.
// acc = b_conv + dinv^2 * h[d] + sum_e coef_e * h[src_e]; writes g_agg.
// ---------------------------------------------------------------------------
__global__ __launch_bounds__(256)
void k_gather(const float* __restrict__ bc, int n) {
    int gwarp = (blockIdx.x * blockDim.x + threadIdx.x) >> 5;
    int lane = threadIdx.x & 31;
    if (gwarp >= n) return;
    int d = gwarp;
    int beg = g_off[d];
    int end = beg + g_cnt[d];

    const float* hlane = g_h + lane * 4;

    // self-loop + bias init
    float di = g_dinv[d];
    float sc = di * di;
    float4 bb = *(const float4*)(bc + lane * 4);
    float4 hd = *(const float4*)(hlane + (size_t)d * H_DIM);
    float4 acc = make_float4(fmaf(sc, hd.x, bb.x), fmaf(sc, hd.y, bb.y),
                             fmaf(sc, hd.z, bb.z), fmaf(sc, hd.w, bb.w));

    for (int base = beg; base < end; base += 32) {
        int idx = base + lane;
        uint2 e = make_uint2(0u, 0u);
        if (idx < end) e = g_edges[idx];
        int cnt = min(32, end - base);
#pragma unroll
        for (int b = 0; b < 32; b += 8) {
            if (b >= cnt) break;
            float4 hv[8];
            float cf[8];
#pragma unroll
            for (int j = 0; j < 8; j++) {
                int s = __shfl_sync(0xFFFFFFFFu, (int)e.x, b + j);
                cf[j] = __shfl_sync(0xFFFFFFFFu, __uint_as_float(e.y), b + j);
                hv[j] = *(const float4*)(hlane + (size_t)s * H_DIM);
            }
#pragma unroll
            for (int j = 0; j < 8; j++) {
                acc.x = fmaf(cf[j], hv[j].x, acc.x);
                acc.y = fmaf(cf[j], hv[j].y, acc.y);
                acc.z = fmaf(cf[j], hv[j].z, acc.z);
                acc.w = fmaf(cf[j], hv[j].w, acc.w);
            }
        }
    }
    *(float4*)(g_agg + (size_t)d * H_DIM + lane * 4) = acc;
}

// ---------------------------------------------------------------------------
extern "C" void kernel_launch(void* const* d_in, const int* in_sizes, int n_in,
                              void* d_out, int out_size) {
    const float* x  = (const float*)d_in[0];
    const int*   ei = (const int*)  d_in[1];
    const float* ew = (const float*)d_in[2];
    const float* Wc = (const float*)d_in[3];  // [512,128]
    const float* bc = (const float*)d_in[4];
    const float* Wl = (const float*)d_in[5];  // [128,512]
    const float* bl = (const float*)d_in[6];
    float* out = (float*)d_out;

    int E = in_sizes[2];
    int n = in_sizes[0] / F_INF;
    const int* src = ei;
    const int* dst = ei + E;

    const int SMEM_BYTES = 98304;
    cudaFuncSetAttribute(mma_gemm<0>, cudaFuncAttributeMaxDynamicSharedMemorySize, SMEM_BYTES);
    cudaFuncSetAttribute(mma_gemm<1>, cudaFuncAttributeMaxDynamicSharedMemorySize, SMEM_BYTES);

    __nv_bfloat16 *wch, *wcl, *wlh, *wll;
    float *dagg;
    cudaGetSymbolAddress((void**)&wch, g_wch);
    cudaGetSymbolAddress((void**)&wcl, g_wcl);
    cudaGetSymbolAddress((void**)&wlh, g_wlh);
    cudaGetSymbolAddress((void**)&wll, g_wll);
    cudaGetSymbolAddress((void**)&dagg, g_agg);

    // 1) degree + histogram
    k_init_deg<<<(n + 255) / 256, 256>>>(n);
    k_deg_accum<<<(E + 255) / 256, 256>>>(dst, ew, E);

    // 2) dinv + bin assignment, fill bins
    k_dinv_assign<<<(n + 255) / 256, 256>>>(n);
    k_fill<<<(E + 255) / 256, 256>>>(src, dst, ew, E);

    // 3) weight splits
    k_split_wT<<<(F_INF * H_DIM + 255) / 256, 256>>>(Wc, wch, wcl, F_INF, H_DIM);
    k_split_wT<<<(F_INF * H_DIM + 255) / 256, 256>>>(Wl, wlh, wll, H_DIM, F_INF);

    // 4) GEMM1: h = x @ Wc
    {
        dim3 grid(1, (n + 127) / 128);
        mma_gemm<0><<<grid, 256, SMEM_BYTES>>>(x, wch, wcl, nullptr, nullptr, n, F_INF);
    }

    // 5) gather-aggregate (atomic-free, self-loop + bias folded in)
    {
        int blocks = (n * 32 + 255) / 256;
        k_gather<<<blocks, 256>>>(bc, n);
    }

    // 6) GEMM2: out = agg @ Wl + b_lin
    {
        dim3 grid(F_INF / 128, (n + 127) / 128);
        mma_gemm<1><<<grid, 256, SMEM_BYTES>>>(dagg, wlh, wll, bl, out, n, H_DIM);
    }
}

// round 7
// speedup vs baseline: 2.3975x; 1.0287x over previous
#include <cuda_runtime.h>
#include <cuda_bf16.h>
#include <cuda_fp16.h>
#include <cstdint>

#define N_NODES 50000
#define F_INF   512
#define H_DIM   128
#define E_MAX   1600000

// ---------------------------------------------------------------------------
// Device scratch (allocation-free rule: device globals)
// ---------------------------------------------------------------------------
__device__ float g_deg [N_NODES];
__device__ float g_dinv[N_NODES];
__device__ int   g_cnt [N_NODES];
__device__ int   g_off [N_NODES];
__device__ int   g_cur [N_NODES];
__device__ int   g_total;
__device__ __align__(16) uint2 g_edges[E_MAX];                     // (src, coef) 12.8 MB
__device__ __align__(16) __half g_h  [(size_t)N_NODES * H_DIM];    // 12.8 MB (fp16!)
__device__ __align__(16) float g_agg [(size_t)N_NODES * H_DIM];    // 25.6 MB
__device__ __align__(16) __nv_bfloat16 g_wch [H_DIM * F_INF];
__device__ __align__(16) __nv_bfloat16 g_wcl [H_DIM * F_INF];
__device__ __align__(16) __nv_bfloat16 g_wlh [F_INF * H_DIM];
__device__ __align__(16) __nv_bfloat16 g_wll [F_INF * H_DIM];

#define SMEM_SWIZZLE_128B(off) ((off) ^ (((off) >> 3) & 0x70))

__device__ __forceinline__ uint32_t smem_to_u32(const void* p) {
    uint32_t a;
    asm("{ .reg .u64 t; cvta.to.shared.u64 t, %1; cvt.u32.u64 %0, t; }"
        : "=r"(a) : "l"(p));
    return a;
}

__device__ __forceinline__ void ldsm_x4(uint32_t* r, uint32_t addr) {
    asm volatile("ldmatrix.sync.aligned.m8n8.x4.shared.b16 {%0,%1,%2,%3}, [%4];"
                 : "=r"(r[0]), "=r"(r[1]), "=r"(r[2]), "=r"(r[3]) : "r"(addr));
}

__device__ __forceinline__ void mma_bf16(float* c, const uint32_t* a,
                                         uint32_t b0, uint32_t b1) {
    asm volatile(
        "mma.sync.aligned.m16n8k16.row.col.f32.bf16.bf16.f32 "
        "{%0,%1,%2,%3}, {%4,%5,%6,%7}, {%8,%9}, {%0,%1,%2,%3};"
        : "+f"(c[0]), "+f"(c[1]), "+f"(c[2]), "+f"(c[3])
        : "r"(a[0]), "r"(a[1]), "r"(a[2]), "r"(a[3]), "r"(b0), "r"(b1));
}

__device__ __forceinline__ uint32_t pack_bf16(float x, float y) {
    __nv_bfloat16 bx = __float2bfloat16(x), by = __float2bfloat16(y);
    return (uint32_t)__bfloat16_as_ushort(bx) |
           ((uint32_t)__bfloat16_as_ushort(by) << 16);
}

__device__ __forceinline__ void cp_async16(uint32_t smem_addr, const void* gptr) {
    asm volatile("cp.async.cg.shared.global [%0], [%1], 16;"
                 :: "r"(smem_addr), "l"(gptr));
}

// ---------------------------------------------------------------------------
// Init: degree/count reset + both weight splits (fused, independent work)
// grid covers 65536 threads.
// ---------------------------------------------------------------------------
__global__ void k_init(const float* __restrict__ Wc, const float* __restrict__ Wl, int n) {
    int i = blockIdx.x * blockDim.x + threadIdx.x;
    if (i < n) { g_deg[i] = 1.0f; g_cnt[i] = 0; }
    if (i == 0) g_total = 0;
    if (i < H_DIM * F_INF) {
        // WcT [128,512]: row=i/512, col=i%512, src Wc[col*128+row]
        int r = i >> 9, c = i & 511;
        float v = Wc[(size_t)c * H_DIM + r];
        __nv_bfloat16 h = __float2bfloat16(v);
        g_wch[i] = h;
        g_wcl[i] = __float2bfloat16(v - __bfloat162float(h));
        // WlT [512,128]: row=i/128, col=i%128, src Wl[col*512+row]
        int r2 = i >> 7, c2 = i & 127;
        float v2 = Wl[(size_t)c2 * F_INF + r2];
        __nv_bfloat16 h2 = __float2bfloat16(v2);
        g_wlh[i] = h2;
        g_wll[i] = __float2bfloat16(v2 - __bfloat162float(h2));
    }
}

__global__ void k_deg_accum(const int* __restrict__ dst, const float* __restrict__ w, int E) {
    int e = blockIdx.x * blockDim.x + threadIdx.x;
    if (e < E) {
        int d = dst[e];
        atomicAdd(&g_deg[d], w[e]);
        atomicAdd(&g_cnt[d], 1);
    }
}

// dinv + warp-aggregated bin-range assignment (order-free)
__global__ void k_dinv_assign(int n) {
    int i = blockIdx.x * blockDim.x + threadIdx.x;
    int lane = threadIdx.x & 31;
    float dg = 0.0f;
    int c = 0;
    if (i < n) {
        dg = g_deg[i];
        g_dinv[i] = (dg > 0.0f) ? rsqrtf(dg) : 0.0f;
        c = g_cnt[i];
    }
    int v = c;
#pragma unroll
    for (int o = 1; o < 32; o <<= 1) {
        int t = __shfl_up_sync(0xFFFFFFFFu, v, o);
        if (lane >= o) v += t;
    }
    int warpTotal = __shfl_sync(0xFFFFFFFFu, v, 31);
    int base = 0;
    if (lane == 31 && warpTotal > 0) base = atomicAdd(&g_total, warpTotal);
    base = __shfl_sync(0xFFFFFFFFu, base, 31);
    if (i < n) {
        int off = base + v - c;
        g_off[i] = off;
        g_cur[i] = off;
    }
}

__global__ void k_fill(const int* __restrict__ src, const int* __restrict__ dst,
                       const float* __restrict__ w, int E) {
    int e = blockIdx.x * blockDim.x + threadIdx.x;
    if (e >= E) return;
    int s = src[e], d = dst[e];
    float coef = g_dinv[s] * __ldg(&w[e]) * g_dinv[d];
    int pos = atomicAdd(&g_cur[d], 1);
    g_edges[pos] = make_uint2((uint32_t)s, __float_as_uint(coef));
}

// ---------------------------------------------------------------------------
// Pipelined mma.sync bf16-split GEMM.
// MODE 0: A = x [M,512], B = WcT -> writes g_h (fp16)
// MODE 1: A = g_agg [M,128], B = WlT -> writes out + b_lin (fp32)
// ---------------------------------------------------------------------------
template <int MODE>
__global__ __launch_bounds__(256)
void mma_gemm(const float* __restrict__ A,
              const __nv_bfloat16* __restrict__ b_hi,
              const __nv_bfloat16* __restrict__ b_lo,
              const float* __restrict__ bias,
              float* __restrict__ outp,
              int M, int K) {
    extern __shared__ char smem[];
    constexpr int SM_AH = 0, SM_AL = 16384;
    constexpr int SM_B0 = 32768, SM_B1 = 65536;

    uint32_t sbase = smem_to_u32(smem);
    int tid = threadIdx.x;
    int wid = tid >> 5, lane = tid & 31;
    int wm = wid & 3, wn = wid >> 2;
    int rowBase = blockIdx.y * 128;
    int colBase = blockIdx.x * 128;

    float acc[2][8][4];
#pragma unroll
    for (int i = 0; i < 2; i++)
#pragma unroll
        for (int j = 0; j < 8; j++)
#pragma unroll
            for (int k = 0; k < 4; k++) acc[i][j][k] = 0.0f;

    uint32_t lr = lane & 7, lg = lane >> 3;
    int nchunk = K >> 6;

    float4 aR[4][2];
    auto ldA = [&](int c) {
        int k0 = c << 6;
#pragma unroll
        for (int l = 0; l < 4; l++) {
            int t = tid + l * 256;
            int r = t >> 3, q = t & 7;
            int grow = rowBase + r;
            float4 v0 = make_float4(0.f, 0.f, 0.f, 0.f), v1 = v0;
            if (grow < M) {
                const float* ap = A + (size_t)grow * K + k0 + q * 8;
                v0 = *(const float4*)ap;
                v1 = *(const float4*)(ap + 4);
            }
            aR[l][0] = v0; aR[l][1] = v1;
        }
    };
    auto stsA = [&]() {
#pragma unroll
        for (int l = 0; l < 4; l++) {
            int t = tid + l * 256;
            int r = t >> 3, q = t & 7;
            float4 v0 = aR[l][0], v1 = aR[l][1];
            uint4 hi, lo;
            hi.x = pack_bf16(v0.x, v0.y); hi.y = pack_bf16(v0.z, v0.w);
            hi.z = pack_bf16(v1.x, v1.y); hi.w = pack_bf16(v1.z, v1.w);
            float r0 = v0.x - __bfloat162float(__ushort_as_bfloat16((unsigned short)(hi.x & 0xFFFF)));
            float r1 = v0.y - __bfloat162float(__ushort_as_bfloat16((unsigned short)(hi.x >> 16)));
            float r2 = v0.z - __bfloat162float(__ushort_as_bfloat16((unsigned short)(hi.y & 0xFFFF)));
            float r3 = v0.w - __bfloat162float(__ushort_as_bfloat16((unsigned short)(hi.y >> 16)));
            float r4 = v1.x - __bfloat162float(__ushort_as_bfloat16((unsigned short)(hi.z & 0xFFFF)));
            float r5 = v1.y - __bfloat162float(__ushort_as_bfloat16((unsigned short)(hi.z >> 16)));
            float r6 = v1.z - __bfloat162float(__ushort_as_bfloat16((unsigned short)(hi.w & 0xFFFF)));
            float r7 = v1.w - __bfloat162float(__ushort_as_bfloat16((unsigned short)(hi.w >> 16)));
            lo.x = pack_bf16(r0, r1); lo.y = pack_bf16(r2, r3);
            lo.z = pack_bf16(r4, r5); lo.w = pack_bf16(r6, r7);
            uint32_t sw = SMEM_SWIZZLE_128B((uint32_t)(r * 128 + q * 16));
            *(uint4*)(smem + SM_AH + sw) = hi;
            *(uint4*)(smem + SM_AL + sw) = lo;
        }
    };
    auto cpB = [&](int c, int buf) {
        int k0 = c << 6;
        int bb = buf ? SM_B1 : SM_B0;
#pragma unroll
        for (int l = 0; l < 8; l++) {
            int t = tid + l * 256;
            int which = t >> 10;
            int r = (t >> 3) & 127, q = t & 7;
            const __nv_bfloat16* sp = which ? b_lo : b_hi;
            const void* gp = sp + (size_t)(colBase + r) * K + k0 + q * 8;
            uint32_t sw = SMEM_SWIZZLE_128B((uint32_t)(r * 128 + q * 16));
            cp_async16(sbase + bb + which * 16384 + sw, gp);
        }
        asm volatile("cp.async.commit_group;" ::: "memory");
    };

    ldA(0);
    cpB(0, 0);

    for (int c = 0; c < nchunk; c++) {
        int buf = c & 1;
        stsA();
        asm volatile("cp.async.wait_group 0;" ::: "memory");
        __syncthreads();
        if (c + 1 < nchunk) { ldA(c + 1); cpB(c + 1, buf ^ 1); }

        int BH = (buf ? SM_B1 : SM_B0);
        int BL = BH + 16384;
#pragma unroll
        for (int s = 0; s < 4; s++) {
            uint32_t ah[2][4], al[2][4], bh[4][4], bl[4][4];
#pragma unroll
            for (int fm = 0; fm < 2; fm++) {
                uint32_t row = (uint32_t)(wm * 32 + fm * 16 + ((lg & 1) << 3) + lr);
                uint32_t kb = (uint32_t)(s * 32 + ((lg >> 1) << 4));
                uint32_t off = SMEM_SWIZZLE_128B(row * 128 + kb);
                ldsm_x4(ah[fm], sbase + SM_AH + off);
                ldsm_x4(al[fm], sbase + SM_AL + off);
            }
#pragma unroll
            for (int fn2 = 0; fn2 < 4; fn2++) {
                uint32_t row = (uint32_t)(wn * 64 + fn2 * 16 + ((lg >> 1) << 3) + lr);
                uint32_t kb = (uint32_t)(s * 32 + ((lg & 1) << 4));
                uint32_t off = SMEM_SWIZZLE_128B(row * 128 + kb);
                ldsm_x4(bh[fn2], sbase + BH + off);
                ldsm_x4(bl[fn2], sbase + BL + off);
            }
#pragma unroll
            for (int fm = 0; fm < 2; fm++)
#pragma unroll
                for (int fn2 = 0; fn2 < 4; fn2++)
#pragma unroll
                    for (int nh = 0; nh < 2; nh++) {
                        float* cc = acc[fm][fn2 * 2 + nh];
                        mma_bf16(cc, ah[fm], bh[fn2][nh * 2], bh[fn2][nh * 2 + 1]);
                        mma_bf16(cc, ah[fm], bl[fn2][nh * 2], bl[fn2][nh * 2 + 1]);
                        mma_bf16(cc, al[fm], bh[fn2][nh * 2], bh[fn2][nh * 2 + 1]);
                    }
        }
        __syncthreads();
    }

    int gq = lane >> 2;
    int tq = lane & 3;
#pragma unroll
    for (int fm = 0; fm < 2; fm++) {
#pragma unroll
        for (int half = 0; half < 2; half++) {
            int row = rowBase + wm * 32 + fm * 16 + half * 8 + gq;
            if (row >= M) continue;
#pragma unroll
            for (int fn = 0; fn < 8; fn++) {
                int col = colBase + wn * 64 + fn * 8 + tq * 2;
                float c0 = acc[fm][fn][half * 2 + 0];
                float c1 = acc[fm][fn][half * 2 + 1];
                if (MODE == 0) {
                    *(__half2*)(g_h + (size_t)row * 128 + col) = __floats2half2_rn(c0, c1);
                } else {
                    float b0 = __ldg(bias + col), b1 = __ldg(bias + col + 1);
                    *(float2*)(outp + (size_t)row * 512 + col) = make_float2(c0 + b0, c1 + b1);
                }
            }
        }
    }
}

// ---------------------------------------------------------------------------
// Gather-aggregate: warp per dst node, fp16 h rows (256B/row), MLP-16.
// acc = b_conv + dinv^2 * h[d] + sum coef_e * h[src_e]  -> g_agg (fp32)
// ---------------------------------------------------------------------------
__global__ __launch_bounds__(256)
void k_gather(const float* __restrict__ bc, int n) {
    int gwarp = (blockIdx.x * blockDim.x + threadIdx.x) >> 5;
    int lane = threadIdx.x & 31;
    if (gwarp >= n) return;
    int d = gwarp;
    int beg = g_off[d];
    int end = beg + g_cnt[d];

    const __half* hlane = g_h + lane * 4;

    float di = g_dinv[d];
    float sc = di * di;
    float4 bb = *(const float4*)(bc + lane * 4);
    uint2 hr = *(const uint2*)(hlane + (size_t)d * H_DIM);
    float2 fa = __half22float2(*reinterpret_cast<__half2*>(&hr.x));
    float2 fb = __half22float2(*reinterpret_cast<__half2*>(&hr.y));
    float4 acc = make_float4(fmaf(sc, fa.x, bb.x), fmaf(sc, fa.y, bb.y),
                             fmaf(sc, fb.x, bb.z), fmaf(sc, fb.y, bb.w));

    for (int base = beg; base < end; base += 32) {
        int idx = base + lane;
        uint2 e = make_uint2(0u, 0u);   // src=0, coef=0 for padding lanes
        if (idx < end) e = g_edges[idx];
        int cnt = min(32, end - base);
#pragma unroll
        for (int b = 0; b < 32; b += 16) {
            if (b >= cnt) break;
            uint2 rv[16];
            float cf[16];
#pragma unroll
            for (int j = 0; j < 16; j++) {
                int s = __shfl_sync(0xFFFFFFFFu, (int)e.x, b + j);
                cf[j] = __shfl_sync(0xFFFFFFFFu, __uint_as_float(e.y), b + j);
                rv[j] = *(const uint2*)(hlane + (size_t)s * H_DIM);
            }
#pragma unroll
            for (int j = 0; j < 16; j++) {
                float2 pa = __half22float2(*reinterpret_cast<__half2*>(&rv[j].x));
                float2 pb = __half22float2(*reinterpret_cast<__half2*>(&rv[j].y));
                acc.x = fmaf(cf[j], pa.x, acc.x);
                acc.y = fmaf(cf[j], pa.y, acc.y);
                acc.z = fmaf(cf[j], pb.x, acc.z);
                acc.w = fmaf(cf[j], pb.y, acc.w);
            }
        }
    }
    *(float4*)(g_agg + (size_t)d * H_DIM + lane * 4) = acc;
}

// ---------------------------------------------------------------------------
extern "C" void kernel_launch(void* const* d_in, const int* in_sizes, int n_in,
                              void* d_out, int out_size) {
    const float* x  = (const float*)d_in[0];
    const int*   ei = (const int*)  d_in[1];
    const float* ew = (const float*)d_in[2];
    const float* Wc = (const float*)d_in[3];  // [512,128]
    const float* bc = (const float*)d_in[4];
    const float* Wl = (const float*)d_in[5];  // [128,512]
    const float* bl = (const float*)d_in[6];
    float* out = (float*)d_out;

    int E = in_sizes[2];
    int n = in_sizes[0] / F_INF;
    const int* src = ei;
    const int* dst = ei + E;

    const int SMEM_BYTES = 98304;
    cudaFuncSetAttribute(mma_gemm<0>, cudaFuncAttributeMaxDynamicSharedMemorySize, SMEM_BYTES);
    cudaFuncSetAttribute(mma_gemm<1>, cudaFuncAttributeMaxDynamicSharedMemorySize, SMEM_BYTES);

    __nv_bfloat16 *wch, *wcl, *wlh, *wll;
    float *dagg;
    cudaGetSymbolAddress((void**)&wch, g_wch);
    cudaGetSymbolAddress((void**)&wcl, g_wcl);
    cudaGetSymbolAddress((void**)&wlh, g_wlh);
    cudaGetSymbolAddress((void**)&wll, g_wll);
    cudaGetSymbolAddress((void**)&dagg, g_agg);

    // 1) init (deg/cnt reset + weight splits fused)
    k_init<<<(H_DIM * F_INF + 255) / 256, 256>>>(Wc, Wl, n);

    // 2) degree + histogram
    k_deg_accum<<<(E + 255) / 256, 256>>>(dst, ew, E);

    // 3) dinv + bin assignment
    k_dinv_assign<<<(n + 255) / 256, 256>>>(n);

    // 4) fill bins with (src, coef)
    k_fill<<<(E + 255) / 256, 256>>>(src, dst, ew, E);

    // 5) GEMM1: h = x @ Wc  (fp16 output)
    {
        dim3 grid(1, (n + 127) / 128);
        mma_gemm<0><<<grid, 256, SMEM_BYTES>>>(x, wch, wcl, nullptr, nullptr, n, F_INF);
    }

    // 6) gather-aggregate (atomic-free, self-loop + bias folded in)  [6th launch -> ncu]
    {
        int blocks = (n * 32 + 255) / 256;
        k_gather<<<blocks, 256>>>(bc, n);
    }

    // 7) GEMM2: out = agg @ Wl + b_lin
    {
        dim3 grid(F_INF / 128, (n + 127) / 128);
        mma_gemm<1><<<grid, 256, SMEM_BYTES>>>(dagg, wlh, wll, bl, out, n, H_DIM);
    }
}

// round 8
// speedup vs baseline: 3.1331x; 1.3068x over previous
#include <cuda_runtime.h>
#include <cuda_bf16.h>
#include <cuda_fp16.h>
#include <cstdint>

#define N_NODES 50000
#define F_INF   512
#define H_DIM   128
#define E_MAX   1600000

// ---------------------------------------------------------------------------
// Device scratch
// ---------------------------------------------------------------------------
__device__ __align__(8) float2 g_deg2[N_NODES];   // {sum_w, count}
__device__ float g_dinv[N_NODES];
__device__ int   g_cnt [N_NODES];
__device__ int   g_off [N_NODES];
__device__ int   g_cur [N_NODES];
__device__ int   g_total;
__device__ __align__(16) uint2  g_edges[E_MAX];                    // (src, coef) 12.8 MB
__device__ __align__(16) __half g_h   [(size_t)N_NODES * H_DIM];   // 12.8 MB
__device__ __align__(16) __half g_aggh[(size_t)N_NODES * H_DIM];   // 12.8 MB
__device__ __align__(16) __nv_bfloat16 g_wch [H_DIM * F_INF];
__device__ __align__(16) __nv_bfloat16 g_wcl [H_DIM * F_INF];
__device__ __align__(16) __half        g_wlh [F_INF * H_DIM];      // Wl^T fp16 single

#define SMEM_SWIZZLE_128B(off) ((off) ^ (((off) >> 3) & 0x70))

__device__ __forceinline__ uint32_t smem_to_u32(const void* p) {
    uint32_t a;
    asm("{ .reg .u64 t; cvta.to.shared.u64 t, %1; cvt.u32.u64 %0, t; }"
        : "=r"(a) : "l"(p));
    return a;
}

__device__ __forceinline__ void ldsm_x4(uint32_t* r, uint32_t addr) {
    asm volatile("ldmatrix.sync.aligned.m8n8.x4.shared.b16 {%0,%1,%2,%3}, [%4];"
                 : "=r"(r[0]), "=r"(r[1]), "=r"(r[2]), "=r"(r[3]) : "r"(addr));
}

__device__ __forceinline__ void mma_bf16(float* c, const uint32_t* a,
                                         uint32_t b0, uint32_t b1) {
    asm volatile(
        "mma.sync.aligned.m16n8k16.row.col.f32.bf16.bf16.f32 "
        "{%0,%1,%2,%3}, {%4,%5,%6,%7}, {%8,%9}, {%0,%1,%2,%3};"
        : "+f"(c[0]), "+f"(c[1]), "+f"(c[2]), "+f"(c[3])
        : "r"(a[0]), "r"(a[1]), "r"(a[2]), "r"(a[3]), "r"(b0), "r"(b1));
}

__device__ __forceinline__ void mma_f16(float* c, const uint32_t* a,
                                        uint32_t b0, uint32_t b1) {
    asm volatile(
        "mma.sync.aligned.m16n8k16.row.col.f32.f16.f16.f32 "
        "{%0,%1,%2,%3}, {%4,%5,%6,%7}, {%8,%9}, {%0,%1,%2,%3};"
        : "+f"(c[0]), "+f"(c[1]), "+f"(c[2]), "+f"(c[3])
        : "r"(a[0]), "r"(a[1]), "r"(a[2]), "r"(a[3]), "r"(b0), "r"(b1));
}

__device__ __forceinline__ uint32_t pack_bf16(float x, float y) {
    __nv_bfloat16 bx = __float2bfloat16(x), by = __float2bfloat16(y);
    return (uint32_t)__bfloat16_as_ushort(bx) |
           ((uint32_t)__bfloat16_as_ushort(by) << 16);
}

__device__ __forceinline__ void cp_async16(uint32_t smem_addr, const void* gptr) {
    asm volatile("cp.async.cg.shared.global [%0], [%1], 16;"
                 :: "r"(smem_addr), "l"(gptr));
}

// ---------------------------------------------------------------------------
// Init: deg2 reset + weight splits (Wc bf16 hi/lo, Wl fp16)
// ---------------------------------------------------------------------------
__global__ void k_init(const float* __restrict__ Wc, const float* __restrict__ Wl, int n) {
    int i = blockIdx.x * blockDim.x + threadIdx.x;
    if (i < n) g_deg2[i] = make_float2(1.0f, 0.0f);
    if (i == 0) g_total = 0;
    if (i < H_DIM * F_INF) {
        int r = i >> 9, c = i & 511;
        float v = Wc[(size_t)c * H_DIM + r];
        __nv_bfloat16 h = __float2bfloat16(v);
        g_wch[i] = h;
        g_wcl[i] = __float2bfloat16(v - __bfloat162float(h));
        int r2 = i >> 7, c2 = i & 127;
        g_wlh[i] = __float2half(Wl[(size_t)c2 * F_INF + r2]);
    }
}

// Single vector reduction per edge: deg += w, cnt += 1
__global__ void k_deg_accum(const int* __restrict__ dst, const float* __restrict__ w, int E) {
    int e = blockIdx.x * blockDim.x + threadIdx.x;
    if (e < E) {
        float2* p = &g_deg2[dst[e]];
        asm volatile("red.global.add.v2.f32 [%0], {%1,%2};"
                     :: "l"(p), "f"(w[e]), "f"(1.0f) : "memory");
    }
}

// dinv + warp-aggregated bin-range assignment
__global__ void k_dinv_assign(int n) {
    int i = blockIdx.x * blockDim.x + threadIdx.x;
    int lane = threadIdx.x & 31;
    int c = 0;
    if (i < n) {
        float2 dg = g_deg2[i];
        g_dinv[i] = (dg.x > 0.0f) ? rsqrtf(dg.x) : 0.0f;
        c = (int)dg.y;
        g_cnt[i] = c;
    }
    int v = c;
#pragma unroll
    for (int o = 1; o < 32; o <<= 1) {
        int t = __shfl_up_sync(0xFFFFFFFFu, v, o);
        if (lane >= o) v += t;
    }
    int warpTotal = __shfl_sync(0xFFFFFFFFu, v, 31);
    int base = 0;
    if (lane == 31 && warpTotal > 0) base = atomicAdd(&g_total, warpTotal);
    base = __shfl_sync(0xFFFFFFFFu, base, 31);
    if (i < n) {
        int off = base + v - c;
        g_off[i] = off;
        g_cur[i] = off;
    }
}

__global__ void k_fill(const int* __restrict__ src, const int* __restrict__ dst,
                       const float* __restrict__ w, int E) {
    int e = blockIdx.x * blockDim.x + threadIdx.x;
    if (e >= E) return;
    int s = src[e], d = dst[e];
    float coef = g_dinv[s] * __ldg(&w[e]) * g_dinv[d];
    int pos = atomicAdd(&g_cur[d], 1);
    g_edges[pos] = make_uint2((uint32_t)s, __float_as_uint(coef));
}

// ---------------------------------------------------------------------------
// GEMM1: h = x @ Wc, bf16 3-pass split, pipelined; writes g_h fp16
// ---------------------------------------------------------------------------
__global__ __launch_bounds__(256)
void gemm1_split(const float* __restrict__ A,
                 const __nv_bfloat16* __restrict__ b_hi,
                 const __nv_bfloat16* __restrict__ b_lo,
                 int M, int K) {
    extern __shared__ char smem[];
    constexpr int SM_AH = 0, SM_AL = 16384;
    constexpr int SM_B0 = 32768, SM_B1 = 65536;

    uint32_t sbase = smem_to_u32(smem);
    int tid = threadIdx.x;
    int wid = tid >> 5, lane = tid & 31;
    int wm = wid & 3, wn = wid >> 2;
    int rowBase = blockIdx.y * 128;
    int colBase = blockIdx.x * 128;

    float acc[2][8][4];
#pragma unroll
    for (int i = 0; i < 2; i++)
#pragma unroll
        for (int j = 0; j < 8; j++)
#pragma unroll
            for (int k = 0; k < 4; k++) acc[i][j][k] = 0.0f;

    uint32_t lr = lane & 7, lg = lane >> 3;
    int nchunk = K >> 6;

    float4 aR[4][2];
    auto ldA = [&](int c) {
        int k0 = c << 6;
#pragma unroll
        for (int l = 0; l < 4; l++) {
            int t = tid + l * 256;
            int r = t >> 3, q = t & 7;
            int grow = rowBase + r;
            float4 v0 = make_float4(0.f, 0.f, 0.f, 0.f), v1 = v0;
            if (grow < M) {
                const float* ap = A + (size_t)grow * K + k0 + q * 8;
                v0 = *(const float4*)ap;
                v1 = *(const float4*)(ap + 4);
            }
            aR[l][0] = v0; aR[l][1] = v1;
        }
    };
    auto stsA = [&]() {
#pragma unroll
        for (int l = 0; l < 4; l++) {
            int t = tid + l * 256;
            int r = t >> 3, q = t & 7;
            float4 v0 = aR[l][0], v1 = aR[l][1];
            uint4 hi, lo;
            hi.x = pack_bf16(v0.x, v0.y); hi.y = pack_bf16(v0.z, v0.w);
            hi.z = pack_bf16(v1.x, v1.y); hi.w = pack_bf16(v1.z, v1.w);
            float r0 = v0.x - __bfloat162float(__ushort_as_bfloat16((unsigned short)(hi.x & 0xFFFF)));
            float r1 = v0.y - __bfloat162float(__ushort_as_bfloat16((unsigned short)(hi.x >> 16)));
            float r2 = v0.z - __bfloat162float(__ushort_as_bfloat16((unsigned short)(hi.y & 0xFFFF)));
            float r3 = v0.w - __bfloat162float(__ushort_as_bfloat16((unsigned short)(hi.y >> 16)));
            float r4 = v1.x - __bfloat162float(__ushort_as_bfloat16((unsigned short)(hi.z & 0xFFFF)));
            float r5 = v1.y - __bfloat162float(__ushort_as_bfloat16((unsigned short)(hi.z >> 16)));
            float r6 = v1.z - __bfloat162float(__ushort_as_bfloat16((unsigned short)(hi.w & 0xFFFF)));
            float r7 = v1.w - __bfloat162float(__ushort_as_bfloat16((unsigned short)(hi.w >> 16)));
            lo.x = pack_bf16(r0, r1); lo.y = pack_bf16(r2, r3);
            lo.z = pack_bf16(r4, r5); lo.w = pack_bf16(r6, r7);
            uint32_t sw = SMEM_SWIZZLE_128B((uint32_t)(r * 128 + q * 16));
            *(uint4*)(smem + SM_AH + sw) = hi;
            *(uint4*)(smem + SM_AL + sw) = lo;
        }
    };
    auto cpB = [&](int c, int buf) {
        int k0 = c << 6;
        int bb = buf ? SM_B1 : SM_B0;
#pragma unroll
        for (int l = 0; l < 8; l++) {
            int t = tid + l * 256;
            int which = t >> 10;
            int r = (t >> 3) & 127, q = t & 7;
            const __nv_bfloat16* sp = which ? b_lo : b_hi;
            const void* gp = sp + (size_t)(colBase + r) * K + k0 + q * 8;
            uint32_t sw = SMEM_SWIZZLE_128B((uint32_t)(r * 128 + q * 16));
            cp_async16(sbase + bb + which * 16384 + sw, gp);
        }
        asm volatile("cp.async.commit_group;" ::: "memory");
    };

    ldA(0);
    cpB(0, 0);

    for (int c = 0; c < nchunk; c++) {
        int buf = c & 1;
        stsA();
        asm volatile("cp.async.wait_group 0;" ::: "memory");
        __syncthreads();
        if (c + 1 < nchunk) { ldA(c + 1); cpB(c + 1, buf ^ 1); }

        int BH = (buf ? SM_B1 : SM_B0);
        int BL = BH + 16384;
#pragma unroll
        for (int s = 0; s < 4; s++) {
            uint32_t ah[2][4], al[2][4], bh[4][4], bl[4][4];
#pragma unroll
            for (int fm = 0; fm < 2; fm++) {
                uint32_t row = (uint32_t)(wm * 32 + fm * 16 + ((lg & 1) << 3) + lr);
                uint32_t kb = (uint32_t)(s * 32 + ((lg >> 1) << 4));
                uint32_t off = SMEM_SWIZZLE_128B(row * 128 + kb);
                ldsm_x4(ah[fm], sbase + SM_AH + off);
                ldsm_x4(al[fm], sbase + SM_AL + off);
            }
#pragma unroll
            for (int fn2 = 0; fn2 < 4; fn2++) {
                uint32_t row = (uint32_t)(wn * 64 + fn2 * 16 + ((lg >> 1) << 3) + lr);
                uint32_t kb = (uint32_t)(s * 32 + ((lg & 1) << 4));
                uint32_t off = SMEM_SWIZZLE_128B(row * 128 + kb);
                ldsm_x4(bh[fn2], sbase + BH + off);
                ldsm_x4(bl[fn2], sbase + BL + off);
            }
#pragma unroll
            for (int fm = 0; fm < 2; fm++)
#pragma unroll
                for (int fn2 = 0; fn2 < 4; fn2++)
#pragma unroll
                    for (int nh = 0; nh < 2; nh++) {
                        float* cc = acc[fm][fn2 * 2 + nh];
                        mma_bf16(cc, ah[fm], bh[fn2][nh * 2], bh[fn2][nh * 2 + 1]);
                        mma_bf16(cc, ah[fm], bl[fn2][nh * 2], bl[fn2][nh * 2 + 1]);
                        mma_bf16(cc, al[fm], bh[fn2][nh * 2], bh[fn2][nh * 2 + 1]);
                    }
        }
        __syncthreads();
    }

    int gq = lane >> 2;
    int tq = lane & 3;
#pragma unroll
    for (int fm = 0; fm < 2; fm++) {
#pragma unroll
        for (int half = 0; half < 2; half++) {
            int row = rowBase + wm * 32 + fm * 16 + half * 8 + gq;
            if (row >= M) continue;
#pragma unroll
            for (int fn = 0; fn < 8; fn++) {
                int col = colBase + wn * 64 + fn * 8 + tq * 2;
                *(__half2*)(g_h + (size_t)row * 128 + col) =
                    __floats2half2_rn(acc[fm][fn][half * 2 + 0], acc[fm][fn][half * 2 + 1]);
            }
        }
    }
}

// ---------------------------------------------------------------------------
// GEMM2: out = agg(fp16) @ Wl(fp16) + b_lin, single-pass fp16 MMA, K=128.
// ---------------------------------------------------------------------------
__global__ __launch_bounds__(256)
void gemm2_f16(const float* __restrict__ bias, float* __restrict__ outp, int M) {
    extern __shared__ char smem[];
    constexpr int SM_A0 = 0, SM_B0 = 16384, SM_A1 = 32768, SM_B1 = 49152;
    uint32_t sbase = smem_to_u32(smem);
    int tid = threadIdx.x;
    int wid = tid >> 5, lane = tid & 31;
    int wm = wid & 3, wn = wid >> 2;
    int rowBase = blockIdx.y * 128;
    int colBase = blockIdx.x * 128;

    float acc[2][8][4];
#pragma unroll
    for (int i = 0; i < 2; i++)
#pragma unroll
        for (int j = 0; j < 8; j++)
#pragma unroll
            for (int k = 0; k < 4; k++) acc[i][j][k] = 0.0f;

    uint32_t lr = lane & 7, lg = lane >> 3;

    auto cpAB = [&](int c, int buf) {
        int k0 = c << 6;
        int ab = buf ? SM_A1 : SM_A0;
        int bb = buf ? SM_B1 : SM_B0;
#pragma unroll
        for (int l = 0; l < 4; l++) {
            int t = tid + l * 256;        // 0..1023
            int r = t >> 3, q = t & 7;
            int grow = rowBase + r;
            if (grow >= M) grow = M - 1;  // rows >= M never stored; value irrelevant
            uint32_t sw = SMEM_SWIZZLE_128B((uint32_t)(r * 128 + q * 16));
            cp_async16(sbase + ab + sw, g_aggh + (size_t)grow * 128 + k0 + q * 8);
            cp_async16(sbase + bb + sw, g_wlh + (size_t)(colBase + r) * 128 + k0 + q * 8);
        }
        asm volatile("cp.async.commit_group;" ::: "memory");
    };

    cpAB(0, 0);
    cpAB(1, 1);

#pragma unroll
    for (int c = 0; c < 2; c++) {
        if (c == 0) asm volatile("cp.async.wait_group 1;" ::: "memory");
        else        asm volatile("cp.async.wait_group 0;" ::: "memory");
        __syncthreads();
        int AHs = c ? SM_A1 : SM_A0;
        int BHs = c ? SM_B1 : SM_B0;
#pragma unroll
        for (int s = 0; s < 4; s++) {
            uint32_t ah[2][4], bh[4][4];
#pragma unroll
            for (int fm = 0; fm < 2; fm++) {
                uint32_t row = (uint32_t)(wm * 32 + fm * 16 + ((lg & 1) << 3) + lr);
                uint32_t kb = (uint32_t)(s * 32 + ((lg >> 1) << 4));
                ldsm_x4(ah[fm], sbase + AHs + SMEM_SWIZZLE_128B(row * 128 + kb));
            }
#pragma unroll
            for (int fn2 = 0; fn2 < 4; fn2++) {
                uint32_t row = (uint32_t)(wn * 64 + fn2 * 16 + ((lg >> 1) << 3) + lr);
                uint32_t kb = (uint32_t)(s * 32 + ((lg & 1) << 4));
                ldsm_x4(bh[fn2], sbase + BHs + SMEM_SWIZZLE_128B(row * 128 + kb));
            }
#pragma unroll
            for (int fm = 0; fm < 2; fm++)
#pragma unroll
                for (int fn2 = 0; fn2 < 4; fn2++)
#pragma unroll
                    for (int nh = 0; nh < 2; nh++)
                        mma_f16(acc[fm][fn2 * 2 + nh], ah[fm],
                                bh[fn2][nh * 2], bh[fn2][nh * 2 + 1]);
        }
        __syncthreads();
    }

    int gq = lane >> 2;
    int tq = lane & 3;
#pragma unroll
    for (int fm = 0; fm < 2; fm++) {
#pragma unroll
        for (int half = 0; half < 2; half++) {
            int row = rowBase + wm * 32 + fm * 16 + half * 8 + gq;
            if (row >= M) continue;
#pragma unroll
            for (int fn = 0; fn < 8; fn++) {
                int col = colBase + wn * 64 + fn * 8 + tq * 2;
                float b0 = __ldg(bias + col), b1 = __ldg(bias + col + 1);
                *(float2*)(outp + (size_t)row * 512 + col) =
                    make_float2(acc[fm][fn][half * 2 + 0] + b0,
                                acc[fm][fn][half * 2 + 1] + b1);
            }
        }
    }
}

// ---------------------------------------------------------------------------
// Gather-aggregate: warp per dst, fp16 rows, MLP-16; writes g_aggh (fp16).
// ---------------------------------------------------------------------------
__global__ __launch_bounds__(256)
void k_gather(const float* __restrict__ bc, int n) {
    int gwarp = (blockIdx.x * blockDim.x + threadIdx.x) >> 5;
    int lane = threadIdx.x & 31;
    if (gwarp >= n) return;
    int d = gwarp;
    int beg = g_off[d];
    int end = beg + g_cnt[d];

    const __half* hlane = g_h + lane * 4;

    float di = g_dinv[d];
    float sc = di * di;
    float4 bb = *(const float4*)(bc + lane * 4);
    uint2 hr = *(const uint2*)(hlane + (size_t)d * H_DIM);
    float2 fa = __half22float2(*reinterpret_cast<__half2*>(&hr.x));
    float2 fb = __half22float2(*reinterpret_cast<__half2*>(&hr.y));
    float4 acc = make_float4(fmaf(sc, fa.x, bb.x), fmaf(sc, fa.y, bb.y),
                             fmaf(sc, fb.x, bb.z), fmaf(sc, fb.y, bb.w));

    for (int base = beg; base < end; base += 32) {
        int idx = base + lane;
        uint2 e = make_uint2(0u, 0u);
        if (idx < end) e = g_edges[idx];
        int cnt = min(32, end - base);
#pragma unroll
        for (int b = 0; b < 32; b += 16) {
            if (b >= cnt) break;
            uint2 rv[16];
            float cf[16];
#pragma unroll
            for (int j = 0; j < 16; j++) {
                int s = __shfl_sync(0xFFFFFFFFu, (int)e.x, b + j);
                cf[j] = __shfl_sync(0xFFFFFFFFu, __uint_as_float(e.y), b + j);
                rv[j] = *(const uint2*)(hlane + (size_t)s * H_DIM);
            }
#pragma unroll
            for (int j = 0; j < 16; j++) {
                float2 pa = __half22float2(*reinterpret_cast<__half2*>(&rv[j].x));
                float2 pb = __half22float2(*reinterpret_cast<__half2*>(&rv[j].y));
                acc.x = fmaf(cf[j], pa.x, acc.x);
                acc.y = fmaf(cf[j], pa.y, acc.y);
                acc.z = fmaf(cf[j], pb.x, acc.z);
                acc.w = fmaf(cf[j], pb.y, acc.w);
            }
        }
    }
    __half2 p0 = __floats2half2_rn(acc.x, acc.y);
    __half2 p1 = __floats2half2_rn(acc.z, acc.w);
    uint2 st;
    st.x = *reinterpret_cast<uint32_t*>(&p0);
    st.y = *reinterpret_cast<uint32_t*>(&p1);
    *(uint2*)(g_aggh + (size_t)d * H_DIM + lane * 4) = st;
}

// ---------------------------------------------------------------------------
extern "C" void kernel_launch(void* const* d_in, const int* in_sizes, int n_in,
                              void* d_out, int out_size) {
    const float* x  = (const float*)d_in[0];
    const int*   ei = (const int*)  d_in[1];
    const float* ew = (const float*)d_in[2];
    const float* Wc = (const float*)d_in[3];  // [512,128]
    const float* bc = (const float*)d_in[4];
    const float* Wl = (const float*)d_in[5];  // [128,512]
    const float* bl = (const float*)d_in[6];
    float* out = (float*)d_out;

    int E = in_sizes[2];
    int n = in_sizes[0] / F_INF;
    const int* src = ei;
    const int* dst = ei + E;

    const int SMEM1 = 98304, SMEM2 = 65536;
    cudaFuncSetAttribute(gemm1_split, cudaFuncAttributeMaxDynamicSharedMemorySize, SMEM1);
    cudaFuncSetAttribute(gemm2_f16,   cudaFuncAttributeMaxDynamicSharedMemorySize, SMEM2);

    __nv_bfloat16 *wch, *wcl;
    cudaGetSymbolAddress((void**)&wch, g_wch);
    cudaGetSymbolAddress((void**)&wcl, g_wcl);

    // 1) init (deg2 reset + weight splits)
    k_init<<<(H_DIM * F_INF + 255) / 256, 256>>>(Wc, Wl, n);

    // 2) degree + count histogram (single v2 reduction per edge)
    k_deg_accum<<<(E + 255) / 256, 256>>>(dst, ew, E);

    // 3) dinv + bin assignment
    k_dinv_assign<<<(n + 255) / 256, 256>>>(n);

    // 4) fill bins with (src, coef)
    k_fill<<<(E + 255) / 256, 256>>>(src, dst, ew, E);

    // 5) GEMM1: h = x @ Wc (bf16 3-pass, fp16 out)
    {
        dim3 grid(1, (n + 127) / 128);
        gemm1_split<<<grid, 256, SMEM1>>>(x, wch, wcl, n, F_INF);
    }

    // 6) gather-aggregate -> fp16 agg
    {
        int blocks = (n * 32 + 255) / 256;
        k_gather<<<blocks, 256>>>(bc, n);
    }

    // 7) GEMM2: out = agg @ Wl + b_lin (single-pass fp16)
    {
        dim3 grid(F_INF / 128, (n + 127) / 128);
        gemm2_f16<<<grid, 256, SMEM2>>>(bl, out, n);
    }
}

// round 9
// speedup vs baseline: 3.6757x; 1.1732x over previous
#include <cuda_runtime.h>
#include <cuda_fp16.h>
#include <cstdint>

#define N_NODES 50000
#define F_INF   512
#define H_DIM   128
#define E_MAX   1600000

// ---------------------------------------------------------------------------
// Device scratch
// ---------------------------------------------------------------------------
__device__ __align__(8) float2 g_deg2[N_NODES];   // {sum_w, count}
__device__ float g_dinv[N_NODES];
__device__ int   g_cnt [N_NODES];
__device__ int   g_off [N_NODES];
__device__ int   g_cur [N_NODES];
__device__ int   g_total;
__device__ __align__(16) uint2  g_edges[E_MAX];                    // (src, coef) 12.8 MB
__device__ __align__(16) __half g_h   [(size_t)N_NODES * H_DIM];   // 12.8 MB
__device__ __align__(16) __half g_aggh[(size_t)N_NODES * H_DIM];   // 12.8 MB
__device__ __align__(16) __half g_wc16[H_DIM * F_INF];             // Wc^T fp16 [128,512]
__device__ __align__(16) __half g_wl16[F_INF * H_DIM];             // Wl^T fp16 [512,128]

#define SMEM_SWIZZLE_128B(off) ((off) ^ (((off) >> 3) & 0x70))

__device__ __forceinline__ uint32_t smem_to_u32(const void* p) {
    uint32_t a;
    asm("{ .reg .u64 t; cvta.to.shared.u64 t, %1; cvt.u32.u64 %0, t; }"
        : "=r"(a) : "l"(p));
    return a;
}

__device__ __forceinline__ void ldsm_x4(uint32_t* r, uint32_t addr) {
    asm volatile("ldmatrix.sync.aligned.m8n8.x4.shared.b16 {%0,%1,%2,%3}, [%4];"
                 : "=r"(r[0]), "=r"(r[1]), "=r"(r[2]), "=r"(r[3]) : "r"(addr));
}

__device__ __forceinline__ void mma_f16(float* c, const uint32_t* a,
                                        uint32_t b0, uint32_t b1) {
    asm volatile(
        "mma.sync.aligned.m16n8k16.row.col.f32.f16.f16.f32 "
        "{%0,%1,%2,%3}, {%4,%5,%6,%7}, {%8,%9}, {%0,%1,%2,%3};"
        : "+f"(c[0]), "+f"(c[1]), "+f"(c[2]), "+f"(c[3])
        : "r"(a[0]), "r"(a[1]), "r"(a[2]), "r"(a[3]), "r"(b0), "r"(b1));
}

__device__ __forceinline__ uint32_t pack_f16(float x, float y) {
    __half2 p = __floats2half2_rn(x, y);
    return *reinterpret_cast<uint32_t*>(&p);
}

__device__ __forceinline__ void cp_async16(uint32_t smem_addr, const void* gptr) {
    asm volatile("cp.async.cg.shared.global [%0], [%1], 16;"
                 :: "r"(smem_addr), "l"(gptr));
}

// ---------------------------------------------------------------------------
// Init: deg2 reset + transposed fp16 weight conversion
// ---------------------------------------------------------------------------
__global__ void k_init(const float* __restrict__ Wc, const float* __restrict__ Wl, int n) {
    int i = blockIdx.x * blockDim.x + threadIdx.x;
    if (i < n) g_deg2[i] = make_float2(1.0f, 0.0f);
    if (i == 0) g_total = 0;
    if (i < H_DIM * F_INF) {
        int r = i >> 9, c = i & 511;                 // WcT [128,512]
        g_wc16[i] = __float2half(Wc[(size_t)c * H_DIM + r]);
        int r2 = i >> 7, c2 = i & 127;               // WlT [512,128]
        g_wl16[i] = __float2half(Wl[(size_t)c2 * F_INF + r2]);
    }
}

// Single vector reduction per edge: deg += w, cnt += 1
__global__ void k_deg_accum(const int* __restrict__ dst, const float* __restrict__ w, int E) {
    int e = blockIdx.x * blockDim.x + threadIdx.x;
    if (e < E) {
        float2* p = &g_deg2[dst[e]];
        asm volatile("red.global.add.v2.f32 [%0], {%1,%2};"
                     :: "l"(p), "f"(w[e]), "f"(1.0f) : "memory");
    }
}

// dinv + warp-aggregated bin-range assignment
__global__ void k_dinv_assign(int n) {
    int i = blockIdx.x * blockDim.x + threadIdx.x;
    int lane = threadIdx.x & 31;
    int c = 0;
    if (i < n) {
        float2 dg = g_deg2[i];
        g_dinv[i] = (dg.x > 0.0f) ? rsqrtf(dg.x) : 0.0f;
        c = (int)dg.y;
        g_cnt[i] = c;
    }
    int v = c;
#pragma unroll
    for (int o = 1; o < 32; o <<= 1) {
        int t = __shfl_up_sync(0xFFFFFFFFu, v, o);
        if (lane >= o) v += t;
    }
    int warpTotal = __shfl_sync(0xFFFFFFFFu, v, 31);
    int base = 0;
    if (lane == 31 && warpTotal > 0) base = atomicAdd(&g_total, warpTotal);
    base = __shfl_sync(0xFFFFFFFFu, base, 31);
    if (i < n) {
        int off = base + v - c;
        g_off[i] = off;
        g_cur[i] = off;
    }
}

__global__ void k_fill(const int* __restrict__ src, const int* __restrict__ dst,
                       const float* __restrict__ w, int E) {
    int e = blockIdx.x * blockDim.x + threadIdx.x;
    if (e >= E) return;
    int s = src[e], d = dst[e];
    float coef = g_dinv[s] * __ldg(&w[e]) * g_dinv[d];
    int pos = atomicAdd(&g_cur[d], 1);
    g_edges[pos] = make_uint2((uint32_t)s, __float_as_uint(coef));
}

// ---------------------------------------------------------------------------
// Unified single-pass fp16 GEMM (fp32 accumulate), 128x128 CTA, 8 warps.
// MODE 0: A = x (fp32, converted in-regs), B = g_wc16, K=512 -> g_h fp16
// MODE 1: A = g_aggh (fp16, cp.async),     B = g_wl16, K=128 -> out fp32 + bias
// ---------------------------------------------------------------------------
template <int MODE>
__global__ __launch_bounds__(256)
void gemm_f16(const float* __restrict__ A32,
              const __half* __restrict__ Bw,
              const float* __restrict__ bias,
              float* __restrict__ outp,
              int M, int K) {
    extern __shared__ char smem[];
    constexpr int SM_A0 = 0, SM_A1 = 16384;      // A1 used only in MODE 1
    constexpr int SM_B0 = 32768, SM_B1 = 49152;

    uint32_t sbase = smem_to_u32(smem);
    int tid = threadIdx.x;
    int wid = tid >> 5, lane = tid & 31;
    int wm = wid & 3, wn = wid >> 2;
    int rowBase = blockIdx.y * 128;
    int colBase = blockIdx.x * 128;

    float acc[2][8][4];
#pragma unroll
    for (int i = 0; i < 2; i++)
#pragma unroll
        for (int j = 0; j < 8; j++)
#pragma unroll
            for (int k = 0; k < 4; k++) acc[i][j][k] = 0.0f;

    uint32_t lr = lane & 7, lg = lane >> 3;
    int nchunk = K >> 6;

    // MODE 0: register-prefetch A (fp32 -> fp16 on STS), single A buffer
    float4 aR[4][2];
    auto ldA = [&](int c) {
        int k0 = c << 6;
#pragma unroll
        for (int l = 0; l < 4; l++) {
            int t = tid + l * 256;
            int r = t >> 3, q = t & 7;
            int grow = rowBase + r;
            float4 v0 = make_float4(0.f, 0.f, 0.f, 0.f), v1 = v0;
            if (grow < M) {
                const float* ap = A32 + (size_t)grow * K + k0 + q * 8;
                v0 = *(const float4*)ap;
                v1 = *(const float4*)(ap + 4);
            }
            aR[l][0] = v0; aR[l][1] = v1;
        }
    };
    auto stsA = [&]() {
#pragma unroll
        for (int l = 0; l < 4; l++) {
            int t = tid + l * 256;
            int r = t >> 3, q = t & 7;
            float4 v0 = aR[l][0], v1 = aR[l][1];
            uint4 hv;
            hv.x = pack_f16(v0.x, v0.y); hv.y = pack_f16(v0.z, v0.w);
            hv.z = pack_f16(v1.x, v1.y); hv.w = pack_f16(v1.z, v1.w);
            uint32_t sw = SMEM_SWIZZLE_128B((uint32_t)(r * 128 + q * 16));
            *(uint4*)(smem + SM_A0 + sw) = hv;
        }
    };
    // MODE 1: cp.async A; both modes: cp.async B
    auto cpA = [&](int c, int buf) {
        int k0 = c << 6;
        int ab = buf ? SM_A1 : SM_A0;
#pragma unroll
        for (int l = 0; l < 4; l++) {
            int t = tid + l * 256;
            int r = t >> 3, q = t & 7;
            int grow = rowBase + r;
            if (grow >= M) grow = M - 1;
            uint32_t sw = SMEM_SWIZZLE_128B((uint32_t)(r * 128 + q * 16));
            cp_async16(sbase + ab + sw, g_aggh + (size_t)grow * 128 + k0 + q * 8);
        }
    };
    auto cpB = [&](int c, int buf) {
        int k0 = c << 6;
        int bb = buf ? SM_B1 : SM_B0;
#pragma unroll
        for (int l = 0; l < 4; l++) {
            int t = tid + l * 256;
            int r = t >> 3, q = t & 7;
            uint32_t sw = SMEM_SWIZZLE_128B((uint32_t)(r * 128 + q * 16));
            cp_async16(sbase + bb + sw, Bw + (size_t)(colBase + r) * K + k0 + q * 8);
        }
    };

    if (MODE == 0) { ldA(0); }
    else           { cpA(0, 0); }
    cpB(0, 0);
    asm volatile("cp.async.commit_group;" ::: "memory");

    for (int c = 0; c < nchunk; c++) {
        int buf = c & 1;
        if (MODE == 0) stsA();
        asm volatile("cp.async.wait_group 0;" ::: "memory");
        __syncthreads();
        if (c + 1 < nchunk) {
            if (MODE == 0) { ldA(c + 1); }
            else           { cpA(c + 1, buf ^ 1); }
            cpB(c + 1, buf ^ 1);
            asm volatile("cp.async.commit_group;" ::: "memory");
        }

        int As = (MODE == 0) ? SM_A0 : (buf ? SM_A1 : SM_A0);
        int Bs = buf ? SM_B1 : SM_B0;
#pragma unroll
        for (int s = 0; s < 4; s++) {
            uint32_t ah[2][4], bh[4][4];
#pragma unroll
            for (int fm = 0; fm < 2; fm++) {
                uint32_t row = (uint32_t)(wm * 32 + fm * 16 + ((lg & 1) << 3) + lr);
                uint32_t kb = (uint32_t)(s * 32 + ((lg >> 1) << 4));
                ldsm_x4(ah[fm], sbase + As + SMEM_SWIZZLE_128B(row * 128 + kb));
            }
#pragma unroll
            for (int fn2 = 0; fn2 < 4; fn2++) {
                uint32_t row = (uint32_t)(wn * 64 + fn2 * 16 + ((lg >> 1) << 3) + lr);
                uint32_t kb = (uint32_t)(s * 32 + ((lg & 1) << 4));
                ldsm_x4(bh[fn2], sbase + Bs + SMEM_SWIZZLE_128B(row * 128 + kb));
            }
#pragma unroll
            for (int fm = 0; fm < 2; fm++)
#pragma unroll
                for (int fn2 = 0; fn2 < 4; fn2++)
#pragma unroll
                    for (int nh = 0; nh < 2; nh++)
                        mma_f16(acc[fm][fn2 * 2 + nh], ah[fm],
                                bh[fn2][nh * 2], bh[fn2][nh * 2 + 1]);
        }
        __syncthreads();
    }

    int gq = lane >> 2;
    int tq = lane & 3;
#pragma unroll
    for (int fm = 0; fm < 2; fm++) {
#pragma unroll
        for (int half = 0; half < 2; half++) {
            int row = rowBase + wm * 32 + fm * 16 + half * 8 + gq;
            if (row >= M) continue;
#pragma unroll
            for (int fn = 0; fn < 8; fn++) {
                int col = colBase + wn * 64 + fn * 8 + tq * 2;
                float c0 = acc[fm][fn][half * 2 + 0];
                float c1 = acc[fm][fn][half * 2 + 1];
                if (MODE == 0) {
                    *(__half2*)(g_h + (size_t)row * 128 + col) = __floats2half2_rn(c0, c1);
                } else {
                    float b0 = __ldg(bias + col), b1 = __ldg(bias + col + 1);
                    *(float2*)(outp + (size_t)row * 512 + col) = make_float2(c0 + b0, c1 + b1);
                }
            }
        }
    }
}

// ---------------------------------------------------------------------------
// Gather-aggregate: warp per dst, fp16 rows, MLP-16; writes g_aggh (fp16).
// ---------------------------------------------------------------------------
__global__ __launch_bounds__(256)
void k_gather(const float* __restrict__ bc, int n) {
    int gwarp = (blockIdx.x * blockDim.x + threadIdx.x) >> 5;
    int lane = threadIdx.x & 31;
    if (gwarp >= n) return;
    int d = gwarp;
    int beg = g_off[d];
    int end = beg + g_cnt[d];

    const __half* hlane = g_h + lane * 4;

    float di = g_dinv[d];
    float sc = di * di;
    float4 bb = *(const float4*)(bc + lane * 4);
    uint2 hr = *(const uint2*)(hlane + (size_t)d * H_DIM);
    float2 fa = __half22float2(*reinterpret_cast<__half2*>(&hr.x));
    float2 fb = __half22float2(*reinterpret_cast<__half2*>(&hr.y));
    float4 acc = make_float4(fmaf(sc, fa.x, bb.x), fmaf(sc, fa.y, bb.y),
                             fmaf(sc, fb.x, bb.z), fmaf(sc, fb.y, bb.w));

    for (int base = beg; base < end; base += 32) {
        int idx = base + lane;
        uint2 e = make_uint2(0u, 0u);
        if (idx < end) e = g_edges[idx];
        int cnt = min(32, end - base);
#pragma unroll
        for (int b = 0; b < 32; b += 16) {
            if (b >= cnt) break;
            uint2 rv[16];
            float cf[16];
#pragma unroll
            for (int j = 0; j < 16; j++) {
                int s = __shfl_sync(0xFFFFFFFFu, (int)e.x, b + j);
                cf[j] = __shfl_sync(0xFFFFFFFFu, __uint_as_float(e.y), b + j);
                rv[j] = *(const uint2*)(hlane + (size_t)s * H_DIM);
            }
#pragma unroll
            for (int j = 0; j < 16; j++) {
                float2 pa = __half22float2(*reinterpret_cast<__half2*>(&rv[j].x));
                float2 pb = __half22float2(*reinterpret_cast<__half2*>(&rv[j].y));
                acc.x = fmaf(cf[j], pa.x, acc.x);
                acc.y = fmaf(cf[j], pa.y, acc.y);
                acc.z = fmaf(cf[j], pb.x, acc.z);
                acc.w = fmaf(cf[j], pb.y, acc.w);
            }
        }
    }
    __half2 p0 = __floats2half2_rn(acc.x, acc.y);
    __half2 p1 = __floats2half2_rn(acc.z, acc.w);
    uint2 st;
    st.x = *reinterpret_cast<uint32_t*>(&p0);
    st.y = *reinterpret_cast<uint32_t*>(&p1);
    *(uint2*)(g_aggh + (size_t)d * H_DIM + lane * 4) = st;
}

// ---------------------------------------------------------------------------
extern "C" void kernel_launch(void* const* d_in, const int* in_sizes, int n_in,
                              void* d_out, int out_size) {
    const float* x  = (const float*)d_in[0];
    const int*   ei = (const int*)  d_in[1];
    const float* ew = (const float*)d_in[2];
    const float* Wc = (const float*)d_in[3];  // [512,128]
    const float* bc = (const float*)d_in[4];
    const float* Wl = (const float*)d_in[5];  // [128,512]
    const float* bl = (const float*)d_in[6];
    float* out = (float*)d_out;

    int E = in_sizes[2];
    int n = in_sizes[0] / F_INF;
    const int* src = ei;
    const int* dst = ei + E;

    const int SMEM_BYTES = 65536;
    cudaFuncSetAttribute(gemm_f16<0>, cudaFuncAttributeMaxDynamicSharedMemorySize, SMEM_BYTES);
    cudaFuncSetAttribute(gemm_f16<1>, cudaFuncAttributeMaxDynamicSharedMemorySize, SMEM_BYTES);

    __half *wc16, *wl16;
    cudaGetSymbolAddress((void**)&wc16, g_wc16);
    cudaGetSymbolAddress((void**)&wl16, g_wl16);

    // 1) init (deg2 reset + fp16 weight transposes)
    k_init<<<(H_DIM * F_INF + 255) / 256, 256>>>(Wc, Wl, n);

    // 2) degree + count histogram
    k_deg_accum<<<(E + 255) / 256, 256>>>(dst, ew, E);

    // 3) dinv + bin assignment
    k_dinv_assign<<<(n + 255) / 256, 256>>>(n);

    // 4) fill bins with (src, coef)
    k_fill<<<(E + 255) / 256, 256>>>(src, dst, ew, E);

    // 5) GEMM1: h = x @ Wc (single-pass fp16)
    {
        dim3 grid(1, (n + 127) / 128);
        gemm_f16<0><<<grid, 256, SMEM_BYTES>>>(x, wc16, nullptr, nullptr, n, F_INF);
    }

    // 6) gather-aggregate -> fp16 agg
    {
        int blocks = (n * 32 + 255) / 256;
        k_gather<<<blocks, 256>>>(bc, n);
    }

    // 7) GEMM2: out = agg @ Wl + b_lin (single-pass fp16)
    {
        dim3 grid(F_INF / 128, (n + 127) / 128);
        gemm_f16<1><<<grid, 256, SMEM_BYTES>>>(nullptr, wl16, bl, out, n, H_DIM);
    }
}

// round 10
// speedup vs baseline: 4.0523x; 1.1025x over previous
#include <cuda_runtime.h>
#include <cuda_fp16.h>
#include <cstdint>

#define N_NODES 50000
#define F_INF   512
#define H_DIM   128
#define E_MAX   1600000

// ---------------------------------------------------------------------------
// Device scratch
// ---------------------------------------------------------------------------
__device__ __align__(8) float2 g_deg2[N_NODES];   // {sum_w, count}
__device__ float g_dinv[N_NODES];
__device__ int   g_cnt [N_NODES];
__device__ int   g_off [N_NODES];
__device__ int   g_cur [N_NODES];
__device__ int   g_total;
__device__ __align__(16) uint2  g_edges[E_MAX];                    // (src, coef) 12.8 MB
__device__ __align__(16) __half g_h   [(size_t)N_NODES * H_DIM];   // 12.8 MB
__device__ __align__(16) __half g_aggh[(size_t)N_NODES * H_DIM];   // 12.8 MB
__device__ __align__(16) __half g_wc16[H_DIM * F_INF];             // Wc^T fp16 [128,512]
__device__ __align__(16) __half g_wl16[F_INF * H_DIM];             // Wl^T fp16 [512,128]

#define SMEM_SWIZZLE_128B(off) ((off) ^ (((off) >> 3) & 0x70))

__device__ __forceinline__ uint32_t smem_to_u32(const void* p) {
    uint32_t a;
    asm("{ .reg .u64 t; cvta.to.shared.u64 t, %1; cvt.u32.u64 %0, t; }"
        : "=r"(a) : "l"(p));
    return a;
}

__device__ __forceinline__ void ldsm_x4(uint32_t* r, uint32_t addr) {
    asm volatile("ldmatrix.sync.aligned.m8n8.x4.shared.b16 {%0,%1,%2,%3}, [%4];"
                 : "=r"(r[0]), "=r"(r[1]), "=r"(r[2]), "=r"(r[3]) : "r"(addr));
}

__device__ __forceinline__ void mma_f16(float* c, const uint32_t* a,
                                        uint32_t b0, uint32_t b1) {
    asm volatile(
        "mma.sync.aligned.m16n8k16.row.col.f32.f16.f16.f32 "
        "{%0,%1,%2,%3}, {%4,%5,%6,%7}, {%8,%9}, {%0,%1,%2,%3};"
        : "+f"(c[0]), "+f"(c[1]), "+f"(c[2]), "+f"(c[3])
        : "r"(a[0]), "r"(a[1]), "r"(a[2]), "r"(a[3]), "r"(b0), "r"(b1));
}

__device__ __forceinline__ uint32_t pack_f16(float x, float y) {
    __half2 p = __floats2half2_rn(x, y);
    return *reinterpret_cast<uint32_t*>(&p);
}

__device__ __forceinline__ void cp_async16(uint32_t smem_addr, const void* gptr) {
    asm volatile("cp.async.cg.shared.global [%0], [%1], 16;"
                 :: "r"(smem_addr), "l"(gptr));
}

// ---------------------------------------------------------------------------
// Init: deg2 reset + transposed fp16 weight conversion
// ---------------------------------------------------------------------------
__global__ void k_init(const float* __restrict__ Wc, const float* __restrict__ Wl, int n) {
    int i = blockIdx.x * blockDim.x + threadIdx.x;
    if (i < n) g_deg2[i] = make_float2(1.0f, 0.0f);
    if (i == 0) g_total = 0;
    if (i < H_DIM * F_INF) {
        int r = i >> 9, c = i & 511;                 // WcT [128,512]
        g_wc16[i] = __float2half(Wc[(size_t)c * H_DIM + r]);
        int r2 = i >> 7, c2 = i & 127;               // WlT [512,128]
        g_wl16[i] = __float2half(Wl[(size_t)c2 * F_INF + r2]);
    }
}

// Single vector reduction per edge: deg += w, cnt += 1
__global__ void k_deg_accum(const int* __restrict__ dst, const float* __restrict__ w, int E) {
    int e = blockIdx.x * blockDim.x + threadIdx.x;
    if (e < E) {
        float2* p = &g_deg2[dst[e]];
        asm volatile("red.global.add.v2.f32 [%0], {%1,%2};"
                     :: "l"(p), "f"(w[e]), "f"(1.0f) : "memory");
    }
}

// dinv + warp-aggregated bin-range assignment
__global__ void k_dinv_assign(int n) {
    int i = blockIdx.x * blockDim.x + threadIdx.x;
    int lane = threadIdx.x & 31;
    int c = 0;
    if (i < n) {
        float2 dg = g_deg2[i];
        g_dinv[i] = (dg.x > 0.0f) ? rsqrtf(dg.x) : 0.0f;
        c = (int)dg.y;
        g_cnt[i] = c;
    }
    int v = c;
#pragma unroll
    for (int o = 1; o < 32; o <<= 1) {
        int t = __shfl_up_sync(0xFFFFFFFFu, v, o);
        if (lane >= o) v += t;
    }
    int warpTotal = __shfl_sync(0xFFFFFFFFu, v, 31);
    int base = 0;
    if (lane == 31 && warpTotal > 0) base = atomicAdd(&g_total, warpTotal);
    base = __shfl_sync(0xFFFFFFFFu, base, 31);
    if (i < n) {
        int off = base + v - c;
        g_off[i] = off;
        g_cur[i] = off;
    }
}

__global__ void k_fill(const int* __restrict__ src, const int* __restrict__ dst,
                       const float* __restrict__ w, int E) {
    int e = blockIdx.x * blockDim.x + threadIdx.x;
    if (e >= E) return;
    int s = src[e], d = dst[e];
    float coef = g_dinv[s] * __ldg(&w[e]) * g_dinv[d];
    int pos = atomicAdd(&g_cur[d], 1);
    g_edges[pos] = make_uint2((uint32_t)s, __float_as_uint(coef));
}

// ---------------------------------------------------------------------------
// Unified single-pass fp16 GEMM (fp32 accumulate), 128x128 CTA, 8 warps.
// MODE 0: A = x (fp32, converted in-regs), B = g_wc16, K=512 -> g_h fp16
// MODE 1: A = g_aggh (fp16, cp.async),     B = g_wl16, K=128 -> out fp32 + bias
// ---------------------------------------------------------------------------
template <int MODE>
__global__ __launch_bounds__(256)
void gemm_f16(const float* __restrict__ A32,
              const __half* __restrict__ Bw,
              const float* __restrict__ bias,
              float* __restrict__ outp,
              int M, int K) {
    extern __shared__ char smem[];
    constexpr int SM_A0 = 0, SM_A1 = 16384;      // A1 used only in MODE 1
    constexpr int SM_B0 = 32768, SM_B1 = 49152;

    uint32_t sbase = smem_to_u32(smem);
    int tid = threadIdx.x;
    int wid = tid >> 5, lane = tid & 31;
    int wm = wid & 3, wn = wid >> 2;
    int rowBase = blockIdx.y * 128;
    int colBase = blockIdx.x * 128;

    float acc[2][8][4];
#pragma unroll
    for (int i = 0; i < 2; i++)
#pragma unroll
        for (int j = 0; j < 8; j++)
#pragma unroll
            for (int k = 0; k < 4; k++) acc[i][j][k] = 0.0f;

    uint32_t lr = lane & 7, lg = lane >> 3;
    int nchunk = K >> 6;

    float4 aR[4][2];
    auto ldA = [&](int c) {
        int k0 = c << 6;
#pragma unroll
        for (int l = 0; l < 4; l++) {
            int t = tid + l * 256;
            int r = t >> 3, q = t & 7;
            int grow = rowBase + r;
            float4 v0 = make_float4(0.f, 0.f, 0.f, 0.f), v1 = v0;
            if (grow < M) {
                const float* ap = A32 + (size_t)grow * K + k0 + q * 8;
                v0 = *(const float4*)ap;
                v1 = *(const float4*)(ap + 4);
            }
            aR[l][0] = v0; aR[l][1] = v1;
        }
    };
    auto stsA = [&]() {
#pragma unroll
        for (int l = 0; l < 4; l++) {
            int t = tid + l * 256;
            int r = t >> 3, q = t & 7;
            float4 v0 = aR[l][0], v1 = aR[l][1];
            uint4 hv;
            hv.x = pack_f16(v0.x, v0.y); hv.y = pack_f16(v0.z, v0.w);
            hv.z = pack_f16(v1.x, v1.y); hv.w = pack_f16(v1.z, v1.w);
            uint32_t sw = SMEM_SWIZZLE_128B((uint32_t)(r * 128 + q * 16));
            *(uint4*)(smem + SM_A0 + sw) = hv;
        }
    };
    auto cpA = [&](int c, int buf) {
        int k0 = c << 6;
        int ab = buf ? SM_A1 : SM_A0;
#pragma unroll
        for (int l = 0; l < 4; l++) {
            int t = tid + l * 256;
            int r = t >> 3, q = t & 7;
            int grow = rowBase + r;
            if (grow >= M) grow = M - 1;
            uint32_t sw = SMEM_SWIZZLE_128B((uint32_t)(r * 128 + q * 16));
            cp_async16(sbase + ab + sw, g_aggh + (size_t)grow * 128 + k0 + q * 8);
        }
    };
    auto cpB = [&](int c, int buf) {
        int k0 = c << 6;
        int bb = buf ? SM_B1 : SM_B0;
#pragma unroll
        for (int l = 0; l < 4; l++) {
            int t = tid + l * 256;
            int r = t >> 3, q = t & 7;
            uint32_t sw = SMEM_SWIZZLE_128B((uint32_t)(r * 128 + q * 16));
            cp_async16(sbase + bb + sw, Bw + (size_t)(colBase + r) * K + k0 + q * 8);
        }
    };

    if (MODE == 0) { ldA(0); }
    else           { cpA(0, 0); }
    cpB(0, 0);
    asm volatile("cp.async.commit_group;" ::: "memory");

    for (int c = 0; c < nchunk; c++) {
        int buf = c & 1;
        if (MODE == 0) stsA();
        asm volatile("cp.async.wait_group 0;" ::: "memory");
        __syncthreads();
        if (c + 1 < nchunk) {
            if (MODE == 0) { ldA(c + 1); }
            else           { cpA(c + 1, buf ^ 1); }
            cpB(c + 1, buf ^ 1);
            asm volatile("cp.async.commit_group;" ::: "memory");
        }

        int As = (MODE == 0) ? SM_A0 : (buf ? SM_A1 : SM_A0);
        int Bs = buf ? SM_B1 : SM_B0;
#pragma unroll
        for (int s = 0; s < 4; s++) {
            uint32_t ah[2][4], bh[4][4];
#pragma unroll
            for (int fm = 0; fm < 2; fm++) {
                uint32_t row = (uint32_t)(wm * 32 + fm * 16 + ((lg & 1) << 3) + lr);
                uint32_t kb = (uint32_t)(s * 32 + ((lg >> 1) << 4));
                ldsm_x4(ah[fm], sbase + As + SMEM_SWIZZLE_128B(row * 128 + kb));
            }
#pragma unroll
            for (int fn2 = 0; fn2 < 4; fn2++) {
                uint32_t row = (uint32_t)(wn * 64 + fn2 * 16 + ((lg >> 1) << 3) + lr);
                uint32_t kb = (uint32_t)(s * 32 + ((lg & 1) << 4));
                ldsm_x4(bh[fn2], sbase + Bs + SMEM_SWIZZLE_128B(row * 128 + kb));
            }
#pragma unroll
            for (int fm = 0; fm < 2; fm++)
#pragma unroll
                for (int fn2 = 0; fn2 < 4; fn2++)
#pragma unroll
                    for (int nh = 0; nh < 2; nh++)
                        mma_f16(acc[fm][fn2 * 2 + nh], ah[fm],
                                bh[fn2][nh * 2], bh[fn2][nh * 2 + 1]);
        }
        __syncthreads();
    }

    int gq = lane >> 2;
    int tq = lane & 3;
#pragma unroll
    for (int fm = 0; fm < 2; fm++) {
#pragma unroll
        for (int half = 0; half < 2; half++) {
            int row = rowBase + wm * 32 + fm * 16 + half * 8 + gq;
            if (row >= M) continue;
#pragma unroll
            for (int fn = 0; fn < 8; fn++) {
                int col = colBase + wn * 64 + fn * 8 + tq * 2;
                float c0 = acc[fm][fn][half * 2 + 0];
                float c1 = acc[fm][fn][half * 2 + 1];
                if (MODE == 0) {
                    *(__half2*)(g_h + (size_t)row * 128 + col) = __floats2half2_rn(c0, c1);
                } else {
                    float b0 = __ldg(bias + col), b1 = __ldg(bias + col + 1);
                    *(float2*)(outp + (size_t)row * 512 + col) = make_float2(c0 + b0, c1 + b1);
                }
            }
        }
    }
}

// ---------------------------------------------------------------------------
// Gather-aggregate: warp per dst, fp16 rows, MLP-16; writes g_aggh (fp16).
// ---------------------------------------------------------------------------
__global__ __launch_bounds__(256)
void k_gather(const float* __restrict__ bc, int n) {
    int gwarp = (blockIdx.x * blockDim.x + threadIdx.x) >> 5;
    int lane = threadIdx.x & 31;
    if (gwarp >= n) return;
    int d = gwarp;
    int beg = g_off[d];
    int end = beg + g_cnt[d];

    const __half* hlane = g_h + lane * 4;

    float di = g_dinv[d];
    float sc = di * di;
    float4 bb = *(const float4*)(bc + lane * 4);
    uint2 hr = *(const uint2*)(hlane + (size_t)d * H_DIM);
    float2 fa = __half22float2(*reinterpret_cast<__half2*>(&hr.x));
    float2 fb = __half22float2(*reinterpret_cast<__half2*>(&hr.y));
    float4 acc = make_float4(fmaf(sc, fa.x, bb.x), fmaf(sc, fa.y, bb.y),
                             fmaf(sc, fb.x, bb.z), fmaf(sc, fb.y, bb.w));

    for (int base = beg; base < end; base += 32) {
        int idx = base + lane;
        uint2 e = make_uint2(0u, 0u);
        if (idx < end) e = g_edges[idx];
        int cnt = min(32, end - base);
#pragma unroll
        for (int b = 0; b < 32; b += 16) {
            if (b >= cnt) break;
            uint2 rv[16];
            float cf[16];
#pragma unroll
            for (int j = 0; j < 16; j++) {
                int s = __shfl_sync(0xFFFFFFFFu, (int)e.x, b + j);
                cf[j] = __shfl_sync(0xFFFFFFFFu, __uint_as_float(e.y), b + j);
                rv[j] = *(const uint2*)(hlane + (size_t)s * H_DIM);
            }
#pragma unroll
            for (int j = 0; j < 16; j++) {
                float2 pa = __half22float2(*reinterpret_cast<__half2*>(&rv[j].x));
                float2 pb = __half22float2(*reinterpret_cast<__half2*>(&rv[j].y));
                acc.x = fmaf(cf[j], pa.x, acc.x);
                acc.y = fmaf(cf[j], pa.y, acc.y);
                acc.z = fmaf(cf[j], pb.x, acc.z);
                acc.w = fmaf(cf[j], pb.y, acc.w);
            }
        }
    }
    __half2 p0 = __floats2half2_rn(acc.x, acc.y);
    __half2 p1 = __floats2half2_rn(acc.z, acc.w);
    uint2 st;
    st.x = *reinterpret_cast<uint32_t*>(&p0);
    st.y = *reinterpret_cast<uint32_t*>(&p1);
    *(uint2*)(g_aggh + (size_t)d * H_DIM + lane * 4) = st;
}

// ---------------------------------------------------------------------------
extern "C" void kernel_launch(void* const* d_in, const int* in_sizes, int n_in,
                              void* d_out, int out_size) {
    const float* x  = (const float*)d_in[0];
    const int*   ei = (const int*)  d_in[1];
    const float* ew = (const float*)d_in[2];
    const float* Wc = (const float*)d_in[3];  // [512,128]
    const float* bc = (const float*)d_in[4];
    const float* Wl = (const float*)d_in[5];  // [128,512]
    const float* bl = (const float*)d_in[6];
    float* out = (float*)d_out;

    int E = in_sizes[2];
    int n = in_sizes[0] / F_INF;
    const int* src = ei;
    const int* dst = ei + E;

    const int SMEM_BYTES = 65536;
    cudaFuncSetAttribute(gemm_f16<0>, cudaFuncAttributeMaxDynamicSharedMemorySize, SMEM_BYTES);
    cudaFuncSetAttribute(gemm_f16<1>, cudaFuncAttributeMaxDynamicSharedMemorySize, SMEM_BYTES);

    __half *wc16, *wl16;
    cudaGetSymbolAddress((void**)&wc16, g_wc16);
    cudaGetSymbolAddress((void**)&wl16, g_wl16);

    // One-time side-stream + events (host resources, not device allocations).
    static cudaStream_t s2 = nullptr;
    static cudaEvent_t evFork = nullptr, evJoin = nullptr;
    if (s2 == nullptr) {
        cudaStreamCreateWithFlags(&s2, cudaStreamNonBlocking);
        cudaEventCreateWithFlags(&evFork, cudaEventDisableTiming);
        cudaEventCreateWithFlags(&evJoin, cudaEventDisableTiming);
    }

    // 1) init (deg2 reset + fp16 weight transposes) — root of both branches
    k_init<<<(H_DIM * F_INF + 255) / 256, 256>>>(Wc, Wl, n);

    // Fork: GEMM1 (needs only x, wc16) runs on s2 concurrently with edge prep.
    cudaEventRecord(evFork, 0);
    cudaStreamWaitEvent(s2, evFork, 0);
    {
        dim3 grid(1, (n + 127) / 128);
        gemm_f16<0><<<grid, 256, SMEM_BYTES, s2>>>(x, wc16, nullptr, nullptr, n, F_INF);
    }

    // Edge-prep branch on the main stream
    k_deg_accum<<<(E + 255) / 256, 256>>>(dst, ew, E);
    k_dinv_assign<<<(n + 255) / 256, 256>>>(n);
    k_fill<<<(E + 255) / 256, 256>>>(src, dst, ew, E);

    // Join: gather needs both g_h (s2) and g_edges/g_off/g_cnt (main)
    cudaEventRecord(evJoin, s2);
    cudaStreamWaitEvent(0, evJoin, 0);

    // gather-aggregate -> fp16 agg
    {
        int blocks = (n * 32 + 255) / 256;
        k_gather<<<blocks, 256>>>(bc, n);
    }

    // GEMM2: out = agg @ Wl + b_lin
    {
        dim3 grid(F_INF / 128, (n + 127) / 128);
        gemm_f16<1><<<grid, 256, SMEM_BYTES>>>(nullptr, wl16, bl, out, n, H_DIM);
    }
}